// round 10
// baseline (speedup 1.0000x reference)
#include <cuda_runtime.h>
#include <cuda_bf16.h>
#include <cuda_fp16.h>
#include <math.h>
#include <cstdint>

// ---------------------------------------------------------------------------
// B=2, N_WAY=5, K_SHOT=5, C=64, H=W=10 (n=100), Q=75, PROJ=64, NHEAD=8
// ALPHAS {8,4,2,1,0.5} -> sum_a exp(-a d) = t + t^2 + t^4 + t^8 + t^16,
// t = exp2(KSCALE * d).  sn arrays store KSCALE*|x|^2; pads = -721 so the
// epilogue needs no masking (t underflows to exactly 0).
// Preproc: 2 blocks/image (pixel halves), proj on bf16 mma.sync.
// Gram: cp.async-pipelined multi-tile blocks, half2 polynomial epilogue.
// ---------------------------------------------------------------------------

#define NSUP_IMG 50
#define NIMG 200
#define NBLK_GRAM 930   /* 750 QS + 30 SS + 150 QQ */

__device__ __align__(16) __nv_bfloat16 g_supB[10 * 512 * 64];
__device__ __align__(16) __nv_bfloat16 g_qryB[150 * 128 * 64];
__device__ __align__(16) float g_snS[10 * 512];
__device__ __align__(16) float g_snQ[150 * 128 + 512];  // +pad for 512-f overreads
__device__ float g_accSS[10];
__device__ float g_accQQ[150];
__device__ float g_accQS[750];
__device__ unsigned int g_done;

#define PRE_SMEM_FLOATS 19456
#define PRE_SMEM_BYTES (PRE_SMEM_FLOATS * 4)
#define GRAM_SMEM_BYTES 70400

#define SMEM_SWIZZLE_128B(off) ((off) ^ (((off) >> 3) & 0x70))
#define KSCALE (-0.72134752044448f)
#define TWO_KSCALE (1.44269504088896f)

__device__ __forceinline__ uint32_t smem_to_u32(const void* p) {
    uint32_t a;
    asm("{ .reg .u64 t; cvta.to.shared.u64 t, %1; cvt.u32.u64 %0, t; }"
        : "=r"(a) : "l"(p));
    return a;
}
__device__ __forceinline__ float ex2f(float x) {
    float y;
    asm("ex2.approx.f32 %0, %1;" : "=f"(y) : "f"(x));
    return y;
}
__device__ __forceinline__ void ldsm_x4(uint32_t& r0, uint32_t& r1,
                                        uint32_t& r2, uint32_t& r3,
                                        uint32_t addr) {
    asm volatile("ldmatrix.sync.aligned.m8n8.x4.shared.b16 {%0,%1,%2,%3}, [%4];"
                 : "=r"(r0), "=r"(r1), "=r"(r2), "=r"(r3) : "r"(addr));
}
__device__ __forceinline__ void ldsm_x2(uint32_t& r0, uint32_t& r1,
                                        uint32_t addr) {
    asm volatile("ldmatrix.sync.aligned.m8n8.x2.shared.b16 {%0,%1}, [%2];"
                 : "=r"(r0), "=r"(r1) : "r"(addr));
}
__device__ __forceinline__ void mma16816(float* d, const uint32_t* a,
                                         const uint32_t* b) {
    asm volatile(
        "mma.sync.aligned.m16n8k16.row.col.f32.bf16.bf16.f32 "
        "{%0,%1,%2,%3}, {%4,%5,%6,%7}, {%8,%9}, {%0,%1,%2,%3};"
        : "+f"(d[0]), "+f"(d[1]), "+f"(d[2]), "+f"(d[3])
        : "r"(a[0]), "r"(a[1]), "r"(a[2]), "r"(a[3]), "r"(b[0]), "r"(b[1]));
}
__device__ __forceinline__ void cp16(uint32_t saddr, const char* g) {
    asm volatile("cp.async.cg.shared.global [%0], [%1], 16;"
                 :: "r"(saddr), "l"(__cvta_generic_to_global(g)) : "memory");
}
#define CP_COMMIT() asm volatile("cp.async.commit_group;" ::: "memory")

// ---------------------------------------------------------------------------
// Fused preproc: 2 blocks per image; each owns 50 pixels.
// Phases 1-2 (W/x staging + 192x112x64 proj GEMM) duplicated per block (cheap,
// tensor-core); phases 3-4 (attention, norm, emit) halved.
// ---------------------------------------------------------------------------
__global__ __launch_bounds__(256, 2)
void preproc_kernel(const float* __restrict__ sup_x,
                    const float* __restrict__ qry_x,
                    const float* __restrict__ Wk,
                    const float* __restrict__ Wq,
                    const float* __restrict__ Wv) {
    extern __shared__ float sm[];
    __nv_bfloat16* aW = (__nv_bfloat16*)sm;          // 192x64 bf16 swizzled
    __nv_bfloat16* xB = (__nv_bfloat16*)(sm + 6144); // 112x64 bf16 swizzled
    float* qs = sm;            // [64][100]
    float* kT = sm + 6400;     // [8][100][8]
    float* vT = sm + 12800;    // [8][100][8]
    float* mean_s = sm + 19200;  // [64] local (50 used)
    float* scal_s = sm + 19328;

    const int img = blockIdx.x >> 1;
    const int halfsel = blockIdx.x & 1;
    const int px0 = halfsel * 50;
    const int tid = threadIdx.x;
    const int wid = tid >> 5, l = tid & 31;

    if (img == 0 && halfsel == 0) {
        if (tid < 10) g_accSS[tid] = 0.f;
        if (tid < 150) g_accQQ[tid] = 0.f;
        for (int t = tid; t < 750; t += 256) g_accQS[t] = 0.f;
        if (tid == 0) g_done = 0u;
    }

    const float* xg = (img < NSUP_IMG) ? (sup_x + (size_t)img * 6400)
                                       : (qry_x + (size_t)(img - NSUP_IMG) * 6400);

    // ---- phase 1a: W -> aW bf16 swizzled (192 rows x 128B) ----
#pragma unroll
    for (int it = 0; it < 12; it++) {
        const int f = tid + it * 256;
        const int row = f >> 4;
        const int q4 = f & 15;
        const float* Wsel = (row < 64) ? Wk : (row < 128) ? Wq : Wv;
        const float4 v = __ldg((const float4*)(Wsel + (row & 63) * 64 + q4 * 4));
        __nv_bfloat162 lo, hi;
        lo.x = __float2bfloat16(v.x); lo.y = __float2bfloat16(v.y);
        hi.x = __float2bfloat16(v.z); hi.y = __float2bfloat16(v.w);
        const int off = row * 128 + q4 * 8;
        const int sw = SMEM_SWIZZLE_128B(off);
        *(__nv_bfloat162*)((char*)aW + sw) = lo;
        *(__nv_bfloat162*)((char*)aW + sw + 4) = hi;
    }
    // ---- phase 1b: x^T -> xB bf16 swizzled; pad rows zero ----
    for (int t = tid; t < 384; t += 256)
        ((uint32_t*)((char*)xB + 100 * 128))[t] = 0u;
#pragma unroll
    for (int it = 0; it < 7; it++) {
        const int f = tid + it * 256;
        if (f < 1600) {
            const int c = f / 25;
            const int n4 = f - c * 25;
            const float4 v = *(const float4*)(xg + c * 100 + n4 * 4);
            const float vv[4] = {v.x, v.y, v.z, v.w};
#pragma unroll
            for (int j = 0; j < 4; j++) {
                const int off = (4 * n4 + j) * 128 + c * 2;
                *(__nv_bfloat16*)((char*)xB + SMEM_SWIZZLE_128B(off)) =
                    __float2bfloat16(vv[j]);
            }
        }
    }
    __syncthreads();

    // ---- phase 2: GEMM D[192][112] = A[192][64] * B[112][64]^T ----
    {
        const int wm = wid & 3, wn = wid >> 2;
        const uint32_t aB = smem_to_u32(aW);
        const uint32_t bB = smem_to_u32(xB);
        float acc[3][7][4];
#pragma unroll
        for (int mi = 0; mi < 3; mi++)
#pragma unroll
            for (int ni = 0; ni < 7; ni++)
#pragma unroll
                for (int e = 0; e < 4; e++) acc[mi][ni][e] = 0.f;

        const int arow_l = l & 15, acol_l = ((l >> 4) & 1) * 16;
        const int brow_l = l & 7, bcol_l = ((l >> 3) & 1) * 16;
#pragma unroll
        for (int ki = 0; ki < 4; ki++) {
            uint32_t af[3][4], bf[7][2];
#pragma unroll
            for (int mi = 0; mi < 3; mi++) {
                const int off =
                    (wm * 48 + mi * 16 + arow_l) * 128 + ki * 32 + acol_l;
                ldsm_x4(af[mi][0], af[mi][1], af[mi][2], af[mi][3],
                        aB + SMEM_SWIZZLE_128B(off));
            }
#pragma unroll
            for (int ni = 0; ni < 7; ni++) {
                const int off =
                    (wn * 56 + ni * 8 + brow_l) * 128 + ki * 32 + bcol_l;
                ldsm_x2(bf[ni][0], bf[ni][1], bB + SMEM_SWIZZLE_128B(off));
            }
#pragma unroll
            for (int mi = 0; mi < 3; mi++)
#pragma unroll
                for (int ni = 0; ni < 7; ni++)
                    mma16816(acc[mi][ni], af[mi], bf[ni]);
        }
        __syncthreads();

#pragma unroll
        for (int mi = 0; mi < 3; mi++) {
            const int rowbase = wm * 48 + mi * 16;
            const int cat = rowbase >> 6;
#pragma unroll
            for (int ni = 0; ni < 7; ni++) {
                const int col0 = wn * 56 + ni * 8 + 2 * (l & 3);
                if (col0 < 100) {
#pragma unroll
                    for (int half = 0; half < 2; half++) {
                        const int r = rowbase + (l >> 2) + half * 8;
                        const float v0 = acc[mi][ni][half * 2];
                        const float v1 = acc[mi][ni][half * 2 + 1];
                        if (cat == 0) {
                            kT[(r >> 3) * 800 + col0 * 8 + (r & 7)] = v0;
                            kT[(r >> 3) * 800 + (col0 + 1) * 8 + (r & 7)] = v1;
                        } else if (cat == 1) {
                            qs[(r - 64) * 100 + col0] = v0;
                            qs[(r - 64) * 100 + col0 + 1] = v1;
                        } else {
                            const int rr = r - 128;
                            vT[(rr >> 3) * 800 + col0 * 8 + (rr & 7)] = v0;
                            vT[(rr >> 3) * 800 + (col0 + 1) * 8 + (rr & 7)] = v1;
                        }
                    }
                }
            }
        }
    }
    __syncthreads();

    // ---- phase 3: single-pass softmax attention, 8 heads x 50 own pixels ----
    const float qscale = 0.3535533905932738f;
    for (int task = tid; task < 400; task += 256) {
        const int h = task / 50;
        const int i = px0 + (task - h * 50);
        const float4* kh = (const float4*)(kT + h * 800);
        const float4* vh = (const float4*)(vT + h * 800);
        float q[8];
#pragma unroll
        for (int d = 0; d < 8; d++) q[d] = qs[(h * 8 + d) * 100 + i] * qscale;

        float Z = 0.f;
        float acc[8];
#pragma unroll
        for (int d = 0; d < 8; d++) acc[d] = 0.f;
#pragma unroll 2
        for (int j = 0; j < 100; j++) {
            const float4 k0 = kh[j * 2], k1 = kh[j * 2 + 1];
            const float s = q[0] * k0.x + q[1] * k0.y + q[2] * k0.z +
                            q[3] * k0.w + q[4] * k1.x + q[5] * k1.y +
                            q[6] * k1.z + q[7] * k1.w;
            const float e = __expf(s);
            Z += e;
            const float4 v0 = vh[j * 2], v1 = vh[j * 2 + 1];
            acc[0] += e * v0.x; acc[1] += e * v0.y;
            acc[2] += e * v0.z; acc[3] += e * v0.w;
            acc[4] += e * v1.x; acc[5] += e * v1.y;
            acc[6] += e * v1.z; acc[7] += e * v1.w;
        }
        const float rz = 1.f / Z;
#pragma unroll
        for (int d = 0; d < 8; d++)
            qs[(h * 8 + d) * 100 + i] =
                acc[d] * rz + __ldg(&xg[(h * 8 + d) * 100 + i]);
    }
    __syncthreads();

    // ---- phase 4: own-50-pixel stats + emit ----
    __nv_bfloat16* featDst;
    float* snDst;
    int padrows;
    if (img < NSUP_IMG) {
        const int b = img / 25, s = img % 25;
        const int way = s / 5, shot = s % 5;
        featDst = g_supB + ((size_t)(b * 5 + way) * 512 + shot * 100) * 64;
        snDst = g_snS + (b * 5 + way) * 512 + shot * 100;
        padrows = (shot == 4) ? 12 : 0;
    } else {
        const int iq = img - NSUP_IMG;
        featDst = g_qryB + (size_t)iq * 128 * 64;
        snDst = g_snQ + iq * 128;
        padrows = 28;
    }

    if (tid < 50) {
        const int pix = px0 + tid;
        float s = 0.f, s2 = 0.f;
        for (int c = 0; c < 64; c++) {
            const float v = qs[c * 100 + pix];
            s += v;
            s2 += v * v;
        }
        const float mu = s * (1.f / 64.f);
        float ss = fmaxf(s2 - s * mu, 0.f);
        const float sc = rsqrtf(ss + 1e-12f);
        mean_s[tid] = mu;
        scal_s[tid] = sc;
        float sb = 0.f;
        for (int c = 0; c < 64; c++) {
            const float f = (qs[c * 100 + pix] - mu) * sc;
            const float fb = __bfloat162float(__float2bfloat16(f));
            sb += fb * fb;
        }
        snDst[pix] = KSCALE * sb;
    }
    __syncthreads();

    for (int idx = tid; idx < 3200; idx += 256) {
        const int ptl = idx >> 6, c = idx & 63;
        const float f = (qs[c * 100 + px0 + ptl] - mean_s[ptl]) * scal_s[ptl];
        featDst[(px0 + ptl) * 64 + c] = __float2bfloat16(f);
    }
    if (padrows && halfsel) {
        for (int t = tid; t < padrows; t += 256) snDst[100 + t] = -721.f;
        for (int t = tid; t < padrows * 64; t += 256)
            featDst[100 * 64 + t] = __float2bfloat16(0.f);
    }
}

// ---------------------------------------------------------------------------
// Multi-tile gram (930 blocks) with half2 polynomial epilogue.
//   [0,750)   QS: 4 tiles | [750,780) SS upper-tri {4,4,2} | [780,930) QQ: 1.
// ---------------------------------------------------------------------------
__constant__ int c_ssI[10] = {0, 0, 0, 0, 1, 1, 1, 2, 2, 3};
__constant__ int c_ssJ[10] = {0, 1, 2, 3, 1, 2, 3, 2, 3, 3};
__constant__ float c_ssW[10] = {1.f, 2.f, 2.f, 2.f, 1.f, 2.f, 2.f, 1.f, 2.f, 1.f};

__global__ __launch_bounds__(256, 2)
void gram_tc(const int* __restrict__ qy, float* __restrict__ out) {
    extern __shared__ char smc[];
    float* snAs = (float*)(smc + 65536);
    float* snBs = (float*)(smc + 67584);
    float* red = (float*)(smc + 69632);
    float* red2 = (float*)(smc + 69664);
    int* sflag = (int*)(smc + 70272);
    const uint32_t smem_base = smem_to_u32(smc);

    const int tid = threadIdx.x;
    const int wid = tid >> 5, l = tid & 31;
    const int bid = blockIdx.x;

    // ---- decode ----
    const char *Abase, *Bbase;
    const float *snAg, *snBg;
    float* outp;
    int T;
    bool jskip;  // j in [104,128) is pure pad (QS/QQ)
    int ti0[4], tj0[4];
    float tw[4];
    if (bid < 750) {
        const int p = bid;
        const int w = p % 5, bq = p / 5, b = bq / 75;
        Abase = (const char*)(g_supB + (size_t)(b * 5 + w) * 512 * 64);
        Bbase = (const char*)(g_qryB + (size_t)bq * 128 * 64);
        snAg = g_snS + (b * 5 + w) * 512;
        snBg = g_snQ + bq * 128;
        outp = &g_accQS[p];
        T = 4;
        jskip = true;
#pragma unroll
        for (int t = 0; t < 4; t++) { ti0[t] = t * 128; tj0[t] = 0; tw[t] = 1.f; }
    } else if (bid < 780) {
        const int g = bid - 750;
        const int p = g / 3, grp = g - p * 3;
        Abase = (const char*)(g_supB + (size_t)p * 512 * 64);
        Bbase = Abase;
        snAg = g_snS + p * 512;
        snBg = snAg;
        outp = &g_accSS[p];
        T = (grp == 2) ? 2 : 4;
        jskip = false;
        const int start = grp * 4;
#pragma unroll
        for (int t = 0; t < 4; t++) {
            const int idx = min(start + t, 9);
            ti0[t] = c_ssI[idx] * 128;
            tj0[t] = c_ssJ[idx] * 128;
            tw[t] = c_ssW[idx];
        }
    } else {
        const int p = bid - 780;
        Abase = (const char*)(g_qryB + (size_t)p * 128 * 64);
        Bbase = Abase;
        snAg = g_snQ + p * 128;
        snBg = snAg;
        outp = &g_accQQ[p];
        T = 1;
        jskip = true;
#pragma unroll
        for (int t = 0; t < 4; t++) { ti0[t] = 0; tj0[t] = 0; tw[t] = 1.f; }
    }

    int loff[4], lsw[4];
#pragma unroll
    for (int it = 0; it < 4; it++) {
        const int idx = it * 256 + tid;
        loff[it] = (idx >> 3) * 128 + (idx & 7) * 16;
        lsw[it] = SMEM_SWIZZLE_128B(loff[it]);
    }

    {
        const char* Ar = Abase + (size_t)ti0[0] * 128;
        const char* Br = Bbase + (size_t)tj0[0] * 128;
#pragma unroll
        for (int it = 0; it < 4; it++) {
            cp16(smem_base + lsw[it], Ar + loff[it]);
            cp16(smem_base + 32768 + lsw[it], Br + loff[it]);
        }
        CP_COMMIT();
    }
    if (T > 1) {
        const char* Ar = Abase + (size_t)ti0[1] * 128;
        const char* Br = Bbase + (size_t)tj0[1] * 128;
#pragma unroll
        for (int it = 0; it < 4; it++) {
            cp16(smem_base + 16384 + lsw[it], Ar + loff[it]);
            cp16(smem_base + 32768 + 16384 + lsw[it], Br + loff[it]);
        }
        CP_COMMIT();
    }

#pragma unroll
    for (int i = 0; i < 2; i++) {
        snAs[tid + i * 256] = snAg[tid + i * 256];
        snBs[tid + i * 256] = snBg[tid + i * 256];
    }

    const int wm = wid & 1, wn = wid >> 1;
    const int arow_l = l & 15;
    const int acol_l = ((l >> 4) & 1) * 16;
    const int brow_l = l & 7;
    const int bcol_l = ((l >> 3) & 1) * 16;
    const int qrow = l >> 2, qcol = (l & 3) * 2;
    // QS/QQ: warps with wn==3 cover j 96..127; only ni==0 (96..103) has
    // any real columns -> skip ni>=1 entirely.
    const int nlim = (jskip && wn == 3) ? 1 : 4;

    float blockSum = 0.f;

#pragma unroll
    for (int t = 0; t < 4; t++) {
        if (t >= T) break;
        if (t + 1 < T)
            asm volatile("cp.async.wait_group 1;" ::: "memory");
        else
            asm volatile("cp.async.wait_group 0;" ::: "memory");
        __syncthreads();

        const uint32_t aBase = smem_base + (t & 1) * 16384;
        const uint32_t bBase = smem_base + 32768 + (t & 1) * 16384;

        float acc[4][4][4];
#pragma unroll
        for (int mi = 0; mi < 4; mi++)
#pragma unroll
            for (int ni = 0; ni < 4; ni++)
#pragma unroll
                for (int e = 0; e < 4; e++) acc[mi][ni][e] = 0.f;

#pragma unroll
        for (int ki = 0; ki < 4; ki++) {
            uint32_t af[4][4], bf[4][2];
#pragma unroll
            for (int mi = 0; mi < 4; mi++) {
                const int off =
                    (wm * 64 + mi * 16 + arow_l) * 128 + ki * 32 + acol_l;
                ldsm_x4(af[mi][0], af[mi][1], af[mi][2], af[mi][3],
                        aBase + SMEM_SWIZZLE_128B(off));
            }
#pragma unroll
            for (int ni = 0; ni < 4; ni++) {
                const int off =
                    (wn * 32 + ni * 8 + brow_l) * 128 + ki * 32 + bcol_l;
                ldsm_x2(bf[ni][0], bf[ni][1], bBase + SMEM_SWIZZLE_128B(off));
            }
#pragma unroll
            for (int mi = 0; mi < 4; mi++)
#pragma unroll
                for (int ni = 0; ni < 4; ni++)
                    mma16816(acc[mi][ni], af[mi], bf[ni]);
        }

        // ---- half2 polynomial epilogue (pad-sn trick, no masking) ----
        float sa2[8], sb2[8];
#pragma unroll
        for (int mi = 0; mi < 4; mi++) {
            sa2[mi * 2 + 0] = snAs[ti0[t] + wm * 64 + mi * 16 + qrow];
            sa2[mi * 2 + 1] = snAs[ti0[t] + wm * 64 + mi * 16 + qrow + 8];
        }
#pragma unroll
        for (int ni = 0; ni < 4; ni++) {
            sb2[ni * 2 + 0] = snBs[tj0[t] + wn * 32 + ni * 8 + qcol];
            sb2[ni * 2 + 1] = snBs[tj0[t] + wn * 32 + ni * 8 + qcol + 1];
        }

        const __half2 one2h = __float2half2_rn(1.f);
        float tileSum = 0.f;
#pragma unroll
        for (int mi = 0; mi < 4; mi++) {
            __half2 accH = __float2half2_rn(0.f);
#pragma unroll
            for (int ni = 0; ni < 4; ni++) {
                if (ni < nlim) {
#pragma unroll
                    for (int hh = 0; hh < 2; hh++) {
                        const float a0 =
                            fmaf(TWO_KSCALE, acc[mi][ni][hh * 2 + 0],
                                 sb2[ni * 2 + 0]) + sa2[mi * 2 + hh];
                        const float a1 =
                            fmaf(TWO_KSCALE, acc[mi][ni][hh * 2 + 1],
                                 sb2[ni * 2 + 1]) + sa2[mi * 2 + hh];
                        const __half2 tt = __floats2half2_rn(ex2f(a0), ex2f(a1));
                        const __half2 t2 = __hmul2(tt, tt);
                        const __half2 t4 = __hmul2(t2, t2);
                        const __half2 t8 = __hmul2(t4, t4);
                        __half2 w = __hfma2(t4, __hadd2(t8, one2h), one2h);
                        w = __hfma2(t2, w, one2h);
                        accH = __hadd2(accH, __hfma2(t2, w, tt));
                    }
                }
            }
            const float2 f2 = __half22float2(accH);
            tileSum += f2.x + f2.y;
        }
        blockSum = fmaf(tw[t], tileSum, blockSum);

        __syncthreads();
        if (t + 2 < T) {
            const char* Ar = Abase + (size_t)ti0[t + 2] * 128;
            const char* Br = Bbase + (size_t)tj0[t + 2] * 128;
#pragma unroll
            for (int it = 0; it < 4; it++) {
                cp16(smem_base + (t & 1) * 16384 + lsw[it], Ar + loff[it]);
                cp16(smem_base + 32768 + (t & 1) * 16384 + lsw[it],
                     Br + loff[it]);
            }
            CP_COMMIT();
        }
    }

#pragma unroll
    for (int o = 16; o; o >>= 1)
        blockSum += __shfl_xor_sync(0xffffffffu, blockSum, o);
    if (l == 0) red[wid] = blockSum;
    __syncthreads();
    if (tid == 0) {
        float tot = 0.f;
#pragma unroll
        for (int w = 0; w < 8; w++) tot += red[w];
        atomicAdd(outp, tot);
        __threadfence();
        const unsigned int old = atomicAdd(&g_done, 1u);
        *sflag = (old == NBLK_GRAM - 1) ? 1 : 0;
    }
    __syncthreads();

    if (*sflag) {
        const int r = tid;
        float val = 0.f;
        if (r < 150) {
            const int b = r / 75;
            const float mq = (__ldcg(&g_accQQ[r]) - 500.f) * (1.f / 9900.f);
            float lg[5];
#pragma unroll
            for (int w = 0; w < 5; w++) {
                const float ms =
                    (__ldcg(&g_accSS[b * 5 + w]) - 2500.f) * (1.f / 249500.f);
                const float msq = (-2.f / 50000.f) * __ldcg(&g_accQS[r * 5 + w]);
                lg[w] = -(ms + mq + msq) * (1.f / 12.5f);
            }
            float m = lg[0];
#pragma unroll
            for (int w = 1; w < 5; w++) m = fmaxf(m, lg[w]);
            float Z = 0.f;
#pragma unroll
            for (int w = 0; w < 5; w++) Z += expf(lg[w] - m);
            const float lse = m + logf(Z);
            val = lse - lg[qy[r]];
        }
        if (r < 152) red2[r] = (r < 150) ? val : 0.f;
        __syncthreads();
        if (r == 0) {
            float s = 0.f;
            for (int i = 0; i < 150; i++) s += red2[i];
            out[0] = s * (1.f / 150.f);
        }
    }
}

// ---------------------------------------------------------------------------
extern "C" void kernel_launch(void* const* d_in, const int* in_sizes, int n_in,
                              void* d_out, int out_size) {
    const float* sup = (const float*)d_in[0];
    const float* qry = (const float*)d_in[1];
    const int* qy = (const int*)d_in[3];
    const float* Wk = (const float*)d_in[4];
    const float* Wq = (const float*)d_in[5];
    const float* Wv = (const float*)d_in[6];

    cudaFuncSetAttribute(preproc_kernel,
                         cudaFuncAttributeMaxDynamicSharedMemorySize,
                         (int)PRE_SMEM_BYTES);
    cudaFuncSetAttribute(gram_tc,
                         cudaFuncAttributeMaxDynamicSharedMemorySize,
                         (int)GRAM_SMEM_BYTES);

    preproc_kernel<<<NIMG * 2, 256, PRE_SMEM_BYTES>>>(sup, qry, Wk, Wq, Wv);
    gram_tc<<<NBLK_GRAM, 256, GRAM_SMEM_BYTES>>>(qy, (float*)d_out);
}

// round 12
// speedup vs baseline: 1.0681x; 1.0681x over previous
#include <cuda_runtime.h>
#include <cuda_bf16.h>
#include <cuda_fp16.h>
#include <math.h>
#include <cstdint>

// ---------------------------------------------------------------------------
// B=2, N_WAY=5, K_SHOT=5, C=64, H=W=10 (n=100), Q=75, PROJ=64, NHEAD=8
// ALPHAS {8,4,2,1,0.5} -> sum_a exp(-a d) = t + t^2 + t^4 + t^8 + t^16,
// t = exp2(KSCALE * d).  sn arrays store KSCALE*|x|^2; pads = -721 so the
// epilogue needs no masking (t underflows to exactly 0).
// Preproc: 1 block/image, proj on bf16 mma.sync (round-9 validated).
// Gram: 128x64 tiles, 32x32 warp tiles, occ-3 (launch_bounds 256,3),
//       cp.async 2-stage pipeline, half2 polynomial epilogue.
// ---------------------------------------------------------------------------

#define NSUP_IMG 50
#define NIMG 200
#define NBLK_GRAM 930   /* 750 QS + 30 SS + 150 QQ */

__device__ __align__(16) __nv_bfloat16 g_supB[10 * 512 * 64];
__device__ __align__(16) __nv_bfloat16 g_qryB[150 * 128 * 64];
__device__ __align__(16) float g_snS[10 * 512];
__device__ __align__(16) float g_snQ[150 * 128 + 512];  // +pad for 512-f overreads
__device__ float g_accSS[10];
__device__ float g_accQQ[150];
__device__ float g_accQS[750];
__device__ unsigned int g_done;

#define PRE_SMEM_FLOATS 19456
#define PRE_SMEM_BYTES (PRE_SMEM_FLOATS * 4)

// gram smem layout (bytes):
//  A0 0 | A1 16384 | B0 32768 | B1 40960 | snA 49152(2048) | snB 51200(2048)
//  red 53248(32) | red2 53280(608) | sflag 53888 | total 53896 -> 54016
#define GRAM_SMEM_BYTES 54016

#define SMEM_SWIZZLE_128B(off) ((off) ^ (((off) >> 3) & 0x70))
#define KSCALE (-0.72134752044448f)
#define TWO_KSCALE (1.44269504088896f)

__device__ __forceinline__ uint32_t smem_to_u32(const void* p) {
    uint32_t a;
    asm("{ .reg .u64 t; cvta.to.shared.u64 t, %1; cvt.u32.u64 %0, t; }"
        : "=r"(a) : "l"(p));
    return a;
}
__device__ __forceinline__ float ex2f(float x) {
    float y;
    asm("ex2.approx.f32 %0, %1;" : "=f"(y) : "f"(x));
    return y;
}
__device__ __forceinline__ void ldsm_x4(uint32_t& r0, uint32_t& r1,
                                        uint32_t& r2, uint32_t& r3,
                                        uint32_t addr) {
    asm volatile("ldmatrix.sync.aligned.m8n8.x4.shared.b16 {%0,%1,%2,%3}, [%4];"
                 : "=r"(r0), "=r"(r1), "=r"(r2), "=r"(r3) : "r"(addr));
}
__device__ __forceinline__ void ldsm_x2(uint32_t& r0, uint32_t& r1,
                                        uint32_t addr) {
    asm volatile("ldmatrix.sync.aligned.m8n8.x2.shared.b16 {%0,%1}, [%2];"
                 : "=r"(r0), "=r"(r1) : "r"(addr));
}
__device__ __forceinline__ void mma16816(float* d, const uint32_t* a,
                                         const uint32_t* b) {
    asm volatile(
        "mma.sync.aligned.m16n8k16.row.col.f32.bf16.bf16.f32 "
        "{%0,%1,%2,%3}, {%4,%5,%6,%7}, {%8,%9}, {%0,%1,%2,%3};"
        : "+f"(d[0]), "+f"(d[1]), "+f"(d[2]), "+f"(d[3])
        : "r"(a[0]), "r"(a[1]), "r"(a[2]), "r"(a[3]), "r"(b[0]), "r"(b[1]));
}
__device__ __forceinline__ void cp16(uint32_t saddr, const char* g) {
    asm volatile("cp.async.cg.shared.global [%0], [%1], 16;"
                 :: "r"(saddr), "l"(__cvta_generic_to_global(g)) : "memory");
}
#define CP_COMMIT() asm volatile("cp.async.commit_group;" ::: "memory")

// ---------------------------------------------------------------------------
// Fused preproc, one block per image (round-9 validated, unchanged).
// ---------------------------------------------------------------------------
__global__ __launch_bounds__(256, 2)
void preproc_kernel(const float* __restrict__ sup_x,
                    const float* __restrict__ qry_x,
                    const float* __restrict__ Wk,
                    const float* __restrict__ Wq,
                    const float* __restrict__ Wv) {
    extern __shared__ float sm[];
    __nv_bfloat16* aW = (__nv_bfloat16*)sm;          // 192x64 bf16 swizzled
    __nv_bfloat16* xB = (__nv_bfloat16*)(sm + 6144); // 112x64 bf16 swizzled
    float* qs = sm;            // [64][100]
    float* kT = sm + 6400;     // [8][100][8]
    float* vT = sm + 12800;    // [8][100][8]
    float* mean_s = sm + 19200;
    float* scal_s = sm + 19328;

    const int img = blockIdx.x;
    const int tid = threadIdx.x;
    const int wid = tid >> 5, l = tid & 31;

    if (img == 0) {
        if (tid < 10) g_accSS[tid] = 0.f;
        if (tid < 150) g_accQQ[tid] = 0.f;
        for (int t = tid; t < 750; t += 256) g_accQS[t] = 0.f;
        if (tid == 0) g_done = 0u;
    }

    const float* xg = (img < NSUP_IMG) ? (sup_x + (size_t)img * 6400)
                                       : (qry_x + (size_t)(img - NSUP_IMG) * 6400);

    // ---- phase 1a: W -> aW bf16 swizzled (192 rows x 128B) ----
#pragma unroll
    for (int it = 0; it < 12; it++) {
        const int f = tid + it * 256;
        const int row = f >> 4;
        const int q4 = f & 15;
        const float* Wsel = (row < 64) ? Wk : (row < 128) ? Wq : Wv;
        const float4 v = __ldg((const float4*)(Wsel + (row & 63) * 64 + q4 * 4));
        __nv_bfloat162 lo, hi;
        lo.x = __float2bfloat16(v.x); lo.y = __float2bfloat16(v.y);
        hi.x = __float2bfloat16(v.z); hi.y = __float2bfloat16(v.w);
        const int off = row * 128 + q4 * 8;
        const int sw = SMEM_SWIZZLE_128B(off);
        *(__nv_bfloat162*)((char*)aW + sw) = lo;
        *(__nv_bfloat162*)((char*)aW + sw + 4) = hi;
    }
    // ---- phase 1b: x^T -> xB bf16 swizzled; pad rows zero ----
    for (int t = tid; t < 384; t += 256)
        ((uint32_t*)((char*)xB + 100 * 128))[t] = 0u;
#pragma unroll
    for (int it = 0; it < 7; it++) {
        const int f = tid + it * 256;
        if (f < 1600) {
            const int c = f / 25;
            const int n4 = f - c * 25;
            const float4 v = *(const float4*)(xg + c * 100 + n4 * 4);
            const float vv[4] = {v.x, v.y, v.z, v.w};
#pragma unroll
            for (int j = 0; j < 4; j++) {
                const int off = (4 * n4 + j) * 128 + c * 2;
                *(__nv_bfloat16*)((char*)xB + SMEM_SWIZZLE_128B(off)) =
                    __float2bfloat16(vv[j]);
            }
        }
    }
    __syncthreads();

    // ---- phase 2: GEMM D[192][112] = A[192][64] * B[112][64]^T ----
    {
        const int wm = wid & 3, wn = wid >> 2;
        const uint32_t aB = smem_to_u32(aW);
        const uint32_t bB = smem_to_u32(xB);
        float acc[3][7][4];
#pragma unroll
        for (int mi = 0; mi < 3; mi++)
#pragma unroll
            for (int ni = 0; ni < 7; ni++)
#pragma unroll
                for (int e = 0; e < 4; e++) acc[mi][ni][e] = 0.f;

        const int arow_l = l & 15, acol_l = ((l >> 4) & 1) * 16;
        const int brow_l = l & 7, bcol_l = ((l >> 3) & 1) * 16;
#pragma unroll
        for (int ki = 0; ki < 4; ki++) {
            uint32_t af[3][4], bf[7][2];
#pragma unroll
            for (int mi = 0; mi < 3; mi++) {
                const int off =
                    (wm * 48 + mi * 16 + arow_l) * 128 + ki * 32 + acol_l;
                ldsm_x4(af[mi][0], af[mi][1], af[mi][2], af[mi][3],
                        aB + SMEM_SWIZZLE_128B(off));
            }
#pragma unroll
            for (int ni = 0; ni < 7; ni++) {
                const int off =
                    (wn * 56 + ni * 8 + brow_l) * 128 + ki * 32 + bcol_l;
                ldsm_x2(bf[ni][0], bf[ni][1], bB + SMEM_SWIZZLE_128B(off));
            }
#pragma unroll
            for (int mi = 0; mi < 3; mi++)
#pragma unroll
                for (int ni = 0; ni < 7; ni++)
                    mma16816(acc[mi][ni], af[mi], bf[ni]);
        }
        __syncthreads();

#pragma unroll
        for (int mi = 0; mi < 3; mi++) {
            const int rowbase = wm * 48 + mi * 16;
            const int cat = rowbase >> 6;
#pragma unroll
            for (int ni = 0; ni < 7; ni++) {
                const int col0 = wn * 56 + ni * 8 + 2 * (l & 3);
                if (col0 < 100) {
#pragma unroll
                    for (int half = 0; half < 2; half++) {
                        const int r = rowbase + (l >> 2) + half * 8;
                        const float v0 = acc[mi][ni][half * 2];
                        const float v1 = acc[mi][ni][half * 2 + 1];
                        if (cat == 0) {
                            kT[(r >> 3) * 800 + col0 * 8 + (r & 7)] = v0;
                            kT[(r >> 3) * 800 + (col0 + 1) * 8 + (r & 7)] = v1;
                        } else if (cat == 1) {
                            qs[(r - 64) * 100 + col0] = v0;
                            qs[(r - 64) * 100 + col0 + 1] = v1;
                        } else {
                            const int rr = r - 128;
                            vT[(rr >> 3) * 800 + col0 * 8 + (rr & 7)] = v0;
                            vT[(rr >> 3) * 800 + (col0 + 1) * 8 + (rr & 7)] = v1;
                        }
                    }
                }
            }
        }
    }
    __syncthreads();

    // ---- phase 3: single-pass softmax attention + residual ----
    const float qscale = 0.3535533905932738f;
    for (int task = tid; task < 800; task += 256) {
        const int h = task / 100;
        const int i = task - h * 100;
        const float4* kh = (const float4*)(kT + h * 800);
        const float4* vh = (const float4*)(vT + h * 800);
        float q[8];
#pragma unroll
        for (int d = 0; d < 8; d++) q[d] = qs[(h * 8 + d) * 100 + i] * qscale;

        float Z = 0.f;
        float acc[8];
#pragma unroll
        for (int d = 0; d < 8; d++) acc[d] = 0.f;
#pragma unroll 2
        for (int j = 0; j < 100; j++) {
            const float4 k0 = kh[j * 2], k1 = kh[j * 2 + 1];
            const float s = q[0] * k0.x + q[1] * k0.y + q[2] * k0.z +
                            q[3] * k0.w + q[4] * k1.x + q[5] * k1.y +
                            q[6] * k1.z + q[7] * k1.w;
            const float e = __expf(s);
            Z += e;
            const float4 v0 = vh[j * 2], v1 = vh[j * 2 + 1];
            acc[0] += e * v0.x; acc[1] += e * v0.y;
            acc[2] += e * v0.z; acc[3] += e * v0.w;
            acc[4] += e * v1.x; acc[5] += e * v1.y;
            acc[6] += e * v1.z; acc[7] += e * v1.w;
        }
        const float rz = 1.f / Z;
#pragma unroll
        for (int d = 0; d < 8; d++)
            qs[(h * 8 + d) * 100 + i] =
                acc[d] * rz + __ldg(&xg[(h * 8 + d) * 100 + i]);
    }
    __syncthreads();

    // ---- phase 4: destination + stats + emit ----
    __nv_bfloat16* featDst;
    float* snDst;
    int padrows;
    if (img < NSUP_IMG) {
        const int b = img / 25, s = img % 25;
        const int way = s / 5, shot = s % 5;
        featDst = g_supB + ((size_t)(b * 5 + way) * 512 + shot * 100) * 64;
        snDst = g_snS + (b * 5 + way) * 512 + shot * 100;
        padrows = (shot == 4) ? 12 : 0;
    } else {
        const int iq = img - NSUP_IMG;
        featDst = g_qryB + (size_t)iq * 128 * 64;
        snDst = g_snQ + iq * 128;
        padrows = 28;
    }

    if (tid < 100) {
        const int pix = tid;
        float s = 0.f, s2 = 0.f;
        for (int c = 0; c < 64; c++) {
            const float v = qs[c * 100 + pix];
            s += v;
            s2 += v * v;
        }
        const float mu = s * (1.f / 64.f);
        float ss = fmaxf(s2 - s * mu, 0.f);
        const float sc = rsqrtf(ss + 1e-12f);
        mean_s[pix] = mu;
        scal_s[pix] = sc;
        float sb = 0.f;
        for (int c = 0; c < 64; c++) {
            const float f = (qs[c * 100 + pix] - mu) * sc;
            const float fb = __bfloat162float(__float2bfloat16(f));
            sb += fb * fb;
        }
        snDst[pix] = KSCALE * sb;
    }
    __syncthreads();

    for (int idx = tid; idx < 6400; idx += 256) {
        const int pt = idx >> 6, c = idx & 63;
        const float f = (qs[c * 100 + pt] - mean_s[pt]) * scal_s[pt];
        featDst[idx] = __float2bfloat16(f);
    }
    if (padrows) {
        for (int t = tid; t < padrows; t += 256) snDst[100 + t] = -721.f;
        for (int t = tid; t < padrows * 64; t += 256)
            featDst[100 * 64 + t] = __float2bfloat16(0.f);
    }
}

// ---------------------------------------------------------------------------
// Gram: 128x64 subtiles, 8 warps as 4x2 (32x32 warp tiles), occ 3.
//   [0,750)   QS: T=8  (i0=(t>>1)*128, j0=(t&1)*64)
//   [750,780) SS: g=bid-750, p=g/3, grp=g%3, T={8,8,4}; pair=grp*4+(t>>1)
//   [780,930) QQ: T=2
// ---------------------------------------------------------------------------
__constant__ int c_ssI[10] = {0, 0, 0, 0, 1, 1, 1, 2, 2, 3};
__constant__ int c_ssJ[10] = {0, 1, 2, 3, 1, 2, 3, 2, 3, 3};
__constant__ float c_ssW[10] = {1.f, 2.f, 2.f, 2.f, 1.f, 2.f, 2.f, 1.f, 2.f, 1.f};

__global__ __launch_bounds__(256, 3)
void gram_tc(const int* __restrict__ qy, float* __restrict__ out) {
    extern __shared__ char smc[];
    float* snAs = (float*)(smc + 49152);
    float* snBs = (float*)(smc + 51200);
    float* red = (float*)(smc + 53248);
    float* red2 = (float*)(smc + 53280);
    int* sflag = (int*)(smc + 53888);
    const uint32_t smem_base = smem_to_u32(smc);

    const int tid = threadIdx.x;
    const int wid = tid >> 5, l = tid & 31;
    const int bid = blockIdx.x;

    // ---- decode ----
    const char *Abase, *Bbase;
    const float *snAg, *snBg;
    float* outp;
    int T, mode, ssStart = 0;
    if (bid < 750) {
        const int p = bid;
        const int w = p % 5, bq = p / 5, b = bq / 75;
        Abase = (const char*)(g_supB + (size_t)(b * 5 + w) * 512 * 64);
        Bbase = (const char*)(g_qryB + (size_t)bq * 128 * 64);
        snAg = g_snS + (b * 5 + w) * 512;
        snBg = g_snQ + bq * 128;
        outp = &g_accQS[p];
        T = 8; mode = 0;
    } else if (bid < 780) {
        const int g = bid - 750;
        const int p = g / 3, grp = g - p * 3;
        Abase = (const char*)(g_supB + (size_t)p * 512 * 64);
        Bbase = Abase;
        snAg = g_snS + p * 512;
        snBg = snAg;
        outp = &g_accSS[p];
        T = (grp == 2) ? 4 : 8; mode = 1; ssStart = grp * 4;
    } else {
        const int p = bid - 780;
        Abase = (const char*)(g_qryB + (size_t)p * 128 * 64);
        Bbase = Abase;
        snAg = g_snQ + p * 128;
        snBg = snAg;
        outp = &g_accQQ[p];
        T = 2; mode = 2;
    }

    // subtile geometry (computed, no register arrays)
    auto geom = [&](int t, int& i0, int& j0, float& w) {
        if (mode == 1) {
            const int pair = ssStart + (t >> 1);
            i0 = c_ssI[pair] * 128;
            j0 = c_ssJ[pair] * 128 + (t & 1) * 64;
            w = c_ssW[pair];
        } else {
            i0 = (mode == 0) ? (t >> 1) * 128 : 0;
            j0 = (t & 1) * 64;
            w = 1.f;
        }
    };

    // per-thread load geometry: A = 4 chunks (16KB), B = 2 chunks (8KB)
    int loffA[4], lswA[4], loffB[2], lswB[2];
#pragma unroll
    for (int it = 0; it < 4; it++) {
        const int idx = it * 256 + tid;
        loffA[it] = (idx >> 3) * 128 + (idx & 7) * 16;
        lswA[it] = SMEM_SWIZZLE_128B(loffA[it]);
    }
#pragma unroll
    for (int it = 0; it < 2; it++) {
        const int idx = it * 256 + tid;
        loffB[it] = (idx >> 3) * 128 + (idx & 7) * 16;
        lswB[it] = SMEM_SWIZZLE_128B(loffB[it]);
    }

    // prologue: tiles 0 and 1 (T >= 2 in all modes)
#pragma unroll
    for (int t = 0; t < 2; t++) {
        int i0, j0; float w;
        geom(t, i0, j0, w);
        const char* Ar = Abase + (size_t)i0 * 128;
        const char* Br = Bbase + (size_t)j0 * 128;
        const uint32_t aOff = smem_base + t * 16384;
        const uint32_t bOff = smem_base + 32768 + t * 8192;
#pragma unroll
        for (int it = 0; it < 4; it++) cp16(aOff + lswA[it], Ar + loffA[it]);
#pragma unroll
        for (int it = 0; it < 2; it++) cp16(bOff + lswB[it], Br + loffB[it]);
        CP_COMMIT();
    }

    // sn staging
#pragma unroll
    for (int i = 0; i < 2; i++) {
        snAs[tid + i * 256] = snAg[tid + i * 256];
        snBs[tid + i * 256] = snBg[tid + i * 256];
    }

    const int wm = wid & 3, wn = wid >> 2;   // 4 x 2: 32 rows x 32 cols
    const int arow_l = l & 15;
    const int acol_l = ((l >> 4) & 1) * 16;
    const int brow_l = l & 7;
    const int bcol_l = ((l >> 3) & 1) * 16;
    const int qrow = l >> 2, qcol = (l & 3) * 2;
    const __half2 one2h = __float2half2_rn(1.f);

    float blockSum = 0.f;

    for (int t = 0; t < T; t++) {
        int i0, j0; float tw;
        geom(t, i0, j0, tw);
        // QS/QQ: j-subtile 1, wn==1 covers j 96..127 -> only ni==0 partially valid
        const int nl = (mode != 1 && (j0 & 64) && wn == 1) ? 1 : 4;

        if (t + 1 < T)
            asm volatile("cp.async.wait_group 1;" ::: "memory");
        else
            asm volatile("cp.async.wait_group 0;" ::: "memory");
        __syncthreads();

        const uint32_t aBase = smem_base + (t & 1) * 16384;
        const uint32_t bBase = smem_base + 32768 + (t & 1) * 8192;

        float acc[2][4][4];
#pragma unroll
        for (int mi = 0; mi < 2; mi++)
#pragma unroll
            for (int ni = 0; ni < 4; ni++)
#pragma unroll
                for (int e = 0; e < 4; e++) acc[mi][ni][e] = 0.f;

#pragma unroll
        for (int ki = 0; ki < 4; ki++) {
            uint32_t af[2][4], bf[4][2];
#pragma unroll
            for (int mi = 0; mi < 2; mi++) {
                const int off =
                    (wm * 32 + mi * 16 + arow_l) * 128 + ki * 32 + acol_l;
                ldsm_x4(af[mi][0], af[mi][1], af[mi][2], af[mi][3],
                        aBase + SMEM_SWIZZLE_128B(off));
            }
#pragma unroll
            for (int ni = 0; ni < 4; ni++) {
                if (ni < nl) {
                    const int off =
                        (wn * 32 + ni * 8 + brow_l) * 128 + ki * 32 + bcol_l;
                    ldsm_x2(bf[ni][0], bf[ni][1],
                            bBase + SMEM_SWIZZLE_128B(off));
                }
            }
#pragma unroll
            for (int mi = 0; mi < 2; mi++)
#pragma unroll
                for (int ni = 0; ni < 4; ni++)
                    if (ni < nl) mma16816(acc[mi][ni], af[mi], bf[ni]);
        }

        // ---- half2 polynomial epilogue ----
        float sa2[4], sb2[8];
#pragma unroll
        for (int mi = 0; mi < 2; mi++) {
            sa2[mi * 2 + 0] = snAs[i0 + wm * 32 + mi * 16 + qrow];
            sa2[mi * 2 + 1] = snAs[i0 + wm * 32 + mi * 16 + qrow + 8];
        }
#pragma unroll
        for (int ni = 0; ni < 4; ni++) {
            sb2[ni * 2 + 0] = snBs[j0 + wn * 32 + ni * 8 + qcol];
            sb2[ni * 2 + 1] = snBs[j0 + wn * 32 + ni * 8 + qcol + 1];
        }

        float tileSum = 0.f;
#pragma unroll
        for (int mi = 0; mi < 2; mi++) {
            __half2 accH = __float2half2_rn(0.f);
#pragma unroll
            for (int ni = 0; ni < 4; ni++) {
                if (ni < nl) {
#pragma unroll
                    for (int hh = 0; hh < 2; hh++) {
                        const float a0 =
                            fmaf(TWO_KSCALE, acc[mi][ni][hh * 2 + 0],
                                 sb2[ni * 2 + 0]) + sa2[mi * 2 + hh];
                        const float a1 =
                            fmaf(TWO_KSCALE, acc[mi][ni][hh * 2 + 1],
                                 sb2[ni * 2 + 1]) + sa2[mi * 2 + hh];
                        const __half2 tt = __floats2half2_rn(ex2f(a0), ex2f(a1));
                        const __half2 t2 = __hmul2(tt, tt);
                        const __half2 t4 = __hmul2(t2, t2);
                        const __half2 t8 = __hmul2(t4, t4);
                        __half2 w = __hfma2(t4, __hadd2(t8, one2h), one2h);
                        w = __hfma2(t2, w, one2h);
                        accH = __hadd2(accH, __hfma2(t2, w, tt));
                    }
                }
            }
            const float2 f2 = __half22float2(accH);
            tileSum += f2.x + f2.y;
        }
        blockSum = fmaf(tw, tileSum, blockSum);

        __syncthreads();  // buf[t&1] reads done before overwrite
        if (t + 2 < T) {
            int i2, j2; float w2;
            geom(t + 2, i2, j2, w2);
            const char* Ar = Abase + (size_t)i2 * 128;
            const char* Br = Bbase + (size_t)j2 * 128;
            const uint32_t aOff = smem_base + (t & 1) * 16384;
            const uint32_t bOff = smem_base + 32768 + (t & 1) * 8192;
#pragma unroll
            for (int it = 0; it < 4; it++)
                cp16(aOff + lswA[it], Ar + loffA[it]);
#pragma unroll
            for (int it = 0; it < 2; it++)
                cp16(bOff + lswB[it], Br + loffB[it]);
            CP_COMMIT();
        }
    }

    // ---- block reduce + atomic ----
#pragma unroll
    for (int o = 16; o; o >>= 1)
        blockSum += __shfl_xor_sync(0xffffffffu, blockSum, o);
    if (l == 0) red[wid] = blockSum;
    __syncthreads();
    if (tid == 0) {
        float tot = 0.f;
#pragma unroll
        for (int w = 0; w < 8; w++) tot += red[w];
        atomicAdd(outp, tot);
        __threadfence();
        const unsigned int old = atomicAdd(&g_done, 1u);
        *sflag = (old == NBLK_GRAM - 1) ? 1 : 0;
    }
    __syncthreads();

    // ---- last finishing block: final loss ----
    if (*sflag) {
        const int r = tid;
        float val = 0.f;
        if (r < 150) {
            const int b = r / 75;
            const float mq = (__ldcg(&g_accQQ[r]) - 500.f) * (1.f / 9900.f);
            float lg[5];
#pragma unroll
            for (int w = 0; w < 5; w++) {
                const float ms =
                    (__ldcg(&g_accSS[b * 5 + w]) - 2500.f) * (1.f / 249500.f);
                const float msq = (-2.f / 50000.f) * __ldcg(&g_accQS[r * 5 + w]);
                lg[w] = -(ms + mq + msq) * (1.f / 12.5f);
            }
            float m = lg[0];
#pragma unroll
            for (int w = 1; w < 5; w++) m = fmaxf(m, lg[w]);
            float Z = 0.f;
#pragma unroll
            for (int w = 0; w < 5; w++) Z += expf(lg[w] - m);
            const float lse = m + logf(Z);
            val = lse - lg[qy[r]];
        }
        if (r < 152) red2[r] = (r < 150) ? val : 0.f;
        __syncthreads();
        if (r == 0) {
            float s = 0.f;
            for (int i = 0; i < 150; i++) s += red2[i];
            out[0] = s * (1.f / 150.f);
        }
    }
}

// ---------------------------------------------------------------------------
extern "C" void kernel_launch(void* const* d_in, const int* in_sizes, int n_in,
                              void* d_out, int out_size) {
    const float* sup = (const float*)d_in[0];
    const float* qry = (const float*)d_in[1];
    const int* qy = (const int*)d_in[3];
    const float* Wk = (const float*)d_in[4];
    const float* Wq = (const float*)d_in[5];
    const float* Wv = (const float*)d_in[6];

    cudaFuncSetAttribute(preproc_kernel,
                         cudaFuncAttributeMaxDynamicSharedMemorySize,
                         (int)PRE_SMEM_BYTES);
    cudaFuncSetAttribute(gram_tc,
                         cudaFuncAttributeMaxDynamicSharedMemorySize,
                         (int)GRAM_SMEM_BYTES);

    preproc_kernel<<<NIMG, 256, PRE_SMEM_BYTES>>>(sup, qry, Wk, Wq, Wv);
    gram_tc<<<NBLK_GRAM, 256, GRAM_SMEM_BYTES>>>(qy, (float*)d_out);
}

// round 13
// speedup vs baseline: 1.0998x; 1.0297x over previous
#include <cuda_runtime.h>
#include <cuda_bf16.h>
#include <cuda_fp16.h>
#include <math.h>
#include <cstdint>

// ---------------------------------------------------------------------------
// B=2, N_WAY=5, K_SHOT=5, C=64, H=W=10 (n=100), Q=75, PROJ=64, NHEAD=8
// ALPHAS {8,4,2,1,0.5} -> sum_a exp(-a d) = t + t^2 + t^4 + t^8 + t^16,
// t = exp2(KSCALE * d).  sn arrays store KSCALE*|x|^2; pads = -721 so the
// epilogue needs no masking (t underflows to exactly 0).
// Preproc: 1 block/image, proj on bf16 mma.sync.
// Gram: 128x64 tiles, 32x32 warp tiles, occ-3, cp.async pipeline,
//       hoisted XOR-swizzle addressing, f16x2 arg/ex2 epilogue.
// ---------------------------------------------------------------------------

#define NSUP_IMG 50
#define NIMG 200
#define NBLK_GRAM 930   /* 750 QS + 30 SS + 150 QQ */

__device__ __align__(16) __nv_bfloat16 g_supB[10 * 512 * 64];
__device__ __align__(16) __nv_bfloat16 g_qryB[150 * 128 * 64];
__device__ __align__(16) float g_snS[10 * 512];
__device__ __align__(16) float g_snQ[150 * 128 + 512];  // +pad for 512-f overreads
__device__ float g_accSS[10];
__device__ float g_accQQ[150];
__device__ float g_accQS[750];
__device__ unsigned int g_done;

#define PRE_SMEM_FLOATS 19456
#define PRE_SMEM_BYTES (PRE_SMEM_FLOATS * 4)

// gram smem layout (bytes):
//  A0 0 | A1 16384 | B0 32768 | B1 40960 | snA 49152(2048) | snB 51200(2048)
//  red 53248(32) | red2 53280(608) | sflag 53888 | total -> 54016
#define GRAM_SMEM_BYTES 54016

#define SMEM_SWIZZLE_128B(off) ((off) ^ (((off) >> 3) & 0x70))
#define KSCALE (-0.72134752044448f)
#define TWO_KSCALE (1.44269504088896f)

__device__ __forceinline__ uint32_t smem_to_u32(const void* p) {
    uint32_t a;
    asm("{ .reg .u64 t; cvta.to.shared.u64 t, %1; cvt.u32.u64 %0, t; }"
        : "=r"(a) : "l"(p));
    return a;
}
__device__ __forceinline__ float ex2f(float x) {
    float y;
    asm("ex2.approx.f32 %0, %1;" : "=f"(y) : "f"(x));
    return y;
}
__device__ __forceinline__ __half2 h2ex2(__half2 x) {
    uint32_t xi, yi;
    xi = *reinterpret_cast<uint32_t*>(&x);
    asm("ex2.approx.f16x2 %0, %1;" : "=r"(yi) : "r"(xi));
    return *reinterpret_cast<__half2*>(&yi);
}
__device__ __forceinline__ void ldsm_x4(uint32_t& r0, uint32_t& r1,
                                        uint32_t& r2, uint32_t& r3,
                                        uint32_t addr) {
    asm volatile("ldmatrix.sync.aligned.m8n8.x4.shared.b16 {%0,%1,%2,%3}, [%4];"
                 : "=r"(r0), "=r"(r1), "=r"(r2), "=r"(r3) : "r"(addr));
}
__device__ __forceinline__ void ldsm_x2(uint32_t& r0, uint32_t& r1,
                                        uint32_t addr) {
    asm volatile("ldmatrix.sync.aligned.m8n8.x2.shared.b16 {%0,%1}, [%2];"
                 : "=r"(r0), "=r"(r1) : "r"(addr));
}
__device__ __forceinline__ void mma16816(float* d, const uint32_t* a,
                                         const uint32_t* b) {
    asm volatile(
        "mma.sync.aligned.m16n8k16.row.col.f32.bf16.bf16.f32 "
        "{%0,%1,%2,%3}, {%4,%5,%6,%7}, {%8,%9}, {%0,%1,%2,%3};"
        : "+f"(d[0]), "+f"(d[1]), "+f"(d[2]), "+f"(d[3])
        : "r"(a[0]), "r"(a[1]), "r"(a[2]), "r"(a[3]), "r"(b[0]), "r"(b[1]));
}
__device__ __forceinline__ void cp16(uint32_t saddr, const char* g) {
    asm volatile("cp.async.cg.shared.global [%0], [%1], 16;"
                 :: "r"(saddr), "l"(__cvta_generic_to_global(g)) : "memory");
}
#define CP_COMMIT() asm volatile("cp.async.commit_group;" ::: "memory")

// ---------------------------------------------------------------------------
// Fused preproc, one block per image (round-12 validated; only change:
// log2(e) folded into qscale so softmax uses raw ex2).
// ---------------------------------------------------------------------------
__global__ __launch_bounds__(256, 2)
void preproc_kernel(const float* __restrict__ sup_x,
                    const float* __restrict__ qry_x,
                    const float* __restrict__ Wk,
                    const float* __restrict__ Wq,
                    const float* __restrict__ Wv) {
    extern __shared__ float sm[];
    __nv_bfloat16* aW = (__nv_bfloat16*)sm;          // 192x64 bf16 swizzled
    __nv_bfloat16* xB = (__nv_bfloat16*)(sm + 6144); // 112x64 bf16 swizzled
    float* qs = sm;            // [64][100]
    float* kT = sm + 6400;     // [8][100][8]
    float* vT = sm + 12800;    // [8][100][8]
    float* mean_s = sm + 19200;
    float* scal_s = sm + 19328;

    const int img = blockIdx.x;
    const int tid = threadIdx.x;
    const int wid = tid >> 5, l = tid & 31;

    if (img == 0) {
        if (tid < 10) g_accSS[tid] = 0.f;
        if (tid < 150) g_accQQ[tid] = 0.f;
        for (int t = tid; t < 750; t += 256) g_accQS[t] = 0.f;
        if (tid == 0) g_done = 0u;
    }

    const float* xg = (img < NSUP_IMG) ? (sup_x + (size_t)img * 6400)
                                       : (qry_x + (size_t)(img - NSUP_IMG) * 6400);

    // ---- phase 1a: W -> aW bf16 swizzled (192 rows x 128B) ----
#pragma unroll
    for (int it = 0; it < 12; it++) {
        const int f = tid + it * 256;
        const int row = f >> 4;
        const int q4 = f & 15;
        const float* Wsel = (row < 64) ? Wk : (row < 128) ? Wq : Wv;
        const float4 v = __ldg((const float4*)(Wsel + (row & 63) * 64 + q4 * 4));
        __nv_bfloat162 lo, hi;
        lo.x = __float2bfloat16(v.x); lo.y = __float2bfloat16(v.y);
        hi.x = __float2bfloat16(v.z); hi.y = __float2bfloat16(v.w);
        const int off = row * 128 + q4 * 8;
        const int sw = SMEM_SWIZZLE_128B(off);
        *(__nv_bfloat162*)((char*)aW + sw) = lo;
        *(__nv_bfloat162*)((char*)aW + sw + 4) = hi;
    }
    // ---- phase 1b: x^T -> xB bf16 swizzled; pad rows zero ----
    for (int t = tid; t < 384; t += 256)
        ((uint32_t*)((char*)xB + 100 * 128))[t] = 0u;
#pragma unroll
    for (int it = 0; it < 7; it++) {
        const int f = tid + it * 256;
        if (f < 1600) {
            const int c = f / 25;
            const int n4 = f - c * 25;
            const float4 v = *(const float4*)(xg + c * 100 + n4 * 4);
            const float vv[4] = {v.x, v.y, v.z, v.w};
#pragma unroll
            for (int j = 0; j < 4; j++) {
                const int off = (4 * n4 + j) * 128 + c * 2;
                *(__nv_bfloat16*)((char*)xB + SMEM_SWIZZLE_128B(off)) =
                    __float2bfloat16(vv[j]);
            }
        }
    }
    __syncthreads();

    // ---- phase 2: GEMM D[192][112] = A[192][64] * B[112][64]^T ----
    {
        const int wm = wid & 3, wn = wid >> 2;
        const uint32_t aB = smem_to_u32(aW);
        const uint32_t bB = smem_to_u32(xB);
        float acc[3][7][4];
#pragma unroll
        for (int mi = 0; mi < 3; mi++)
#pragma unroll
            for (int ni = 0; ni < 7; ni++)
#pragma unroll
                for (int e = 0; e < 4; e++) acc[mi][ni][e] = 0.f;

        const int arow_l = l & 15, acol_l = ((l >> 4) & 1) * 16;
        const int brow_l = l & 7, bcol_l = ((l >> 3) & 1) * 16;
#pragma unroll
        for (int ki = 0; ki < 4; ki++) {
            uint32_t af[3][4], bf[7][2];
#pragma unroll
            for (int mi = 0; mi < 3; mi++) {
                const int off =
                    (wm * 48 + mi * 16 + arow_l) * 128 + ki * 32 + acol_l;
                ldsm_x4(af[mi][0], af[mi][1], af[mi][2], af[mi][3],
                        aB + SMEM_SWIZZLE_128B(off));
            }
#pragma unroll
            for (int ni = 0; ni < 7; ni++) {
                const int off =
                    (wn * 56 + ni * 8 + brow_l) * 128 + ki * 32 + bcol_l;
                ldsm_x2(bf[ni][0], bf[ni][1], bB + SMEM_SWIZZLE_128B(off));
            }
#pragma unroll
            for (int mi = 0; mi < 3; mi++)
#pragma unroll
                for (int ni = 0; ni < 7; ni++)
                    mma16816(acc[mi][ni], af[mi], bf[ni]);
        }
        __syncthreads();

#pragma unroll
        for (int mi = 0; mi < 3; mi++) {
            const int rowbase = wm * 48 + mi * 16;
            const int cat = rowbase >> 6;
#pragma unroll
            for (int ni = 0; ni < 7; ni++) {
                const int col0 = wn * 56 + ni * 8 + 2 * (l & 3);
                if (col0 < 100) {
#pragma unroll
                    for (int half = 0; half < 2; half++) {
                        const int r = rowbase + (l >> 2) + half * 8;
                        const float v0 = acc[mi][ni][half * 2];
                        const float v1 = acc[mi][ni][half * 2 + 1];
                        if (cat == 0) {
                            kT[(r >> 3) * 800 + col0 * 8 + (r & 7)] = v0;
                            kT[(r >> 3) * 800 + (col0 + 1) * 8 + (r & 7)] = v1;
                        } else if (cat == 1) {
                            qs[(r - 64) * 100 + col0] = v0;
                            qs[(r - 64) * 100 + col0 + 1] = v1;
                        } else {
                            const int rr = r - 128;
                            vT[(rr >> 3) * 800 + col0 * 8 + (rr & 7)] = v0;
                            vT[(rr >> 3) * 800 + (col0 + 1) * 8 + (rr & 7)] = v1;
                        }
                    }
                }
            }
        }
    }
    __syncthreads();

    // ---- phase 3: single-pass softmax attention + residual ----
    // log2(e)/sqrt(8) folded into q so e = ex2(s) directly.
    const float qscale = 0.51011856f;
    for (int task = tid; task < 800; task += 256) {
        const int h = task / 100;
        const int i = task - h * 100;
        const float4* kh = (const float4*)(kT + h * 800);
        const float4* vh = (const float4*)(vT + h * 800);
        float q[8];
#pragma unroll
        for (int d = 0; d < 8; d++) q[d] = qs[(h * 8 + d) * 100 + i] * qscale;

        float Z = 0.f;
        float acc[8];
#pragma unroll
        for (int d = 0; d < 8; d++) acc[d] = 0.f;
#pragma unroll 2
        for (int j = 0; j < 100; j++) {
            const float4 k0 = kh[j * 2], k1 = kh[j * 2 + 1];
            const float s = q[0] * k0.x + q[1] * k0.y + q[2] * k0.z +
                            q[3] * k0.w + q[4] * k1.x + q[5] * k1.y +
                            q[6] * k1.z + q[7] * k1.w;
            const float e = ex2f(s);
            Z += e;
            const float4 v0 = vh[j * 2], v1 = vh[j * 2 + 1];
            acc[0] += e * v0.x; acc[1] += e * v0.y;
            acc[2] += e * v0.z; acc[3] += e * v0.w;
            acc[4] += e * v1.x; acc[5] += e * v1.y;
            acc[6] += e * v1.z; acc[7] += e * v1.w;
        }
        const float rz = 1.f / Z;
#pragma unroll
        for (int d = 0; d < 8; d++)
            qs[(h * 8 + d) * 100 + i] =
                acc[d] * rz + __ldg(&xg[(h * 8 + d) * 100 + i]);
    }
    __syncthreads();

    // ---- phase 4: destination + stats + emit ----
    __nv_bfloat16* featDst;
    float* snDst;
    int padrows;
    if (img < NSUP_IMG) {
        const int b = img / 25, s = img % 25;
        const int way = s / 5, shot = s % 5;
        featDst = g_supB + ((size_t)(b * 5 + way) * 512 + shot * 100) * 64;
        snDst = g_snS + (b * 5 + way) * 512 + shot * 100;
        padrows = (shot == 4) ? 12 : 0;
    } else {
        const int iq = img - NSUP_IMG;
        featDst = g_qryB + (size_t)iq * 128 * 64;
        snDst = g_snQ + iq * 128;
        padrows = 28;
    }

    if (tid < 100) {
        const int pix = tid;
        float s = 0.f, s2 = 0.f;
        for (int c = 0; c < 64; c++) {
            const float v = qs[c * 100 + pix];
            s += v;
            s2 += v * v;
        }
        const float mu = s * (1.f / 64.f);
        float ss = fmaxf(s2 - s * mu, 0.f);
        const float sc = rsqrtf(ss + 1e-12f);
        mean_s[pix] = mu;
        scal_s[pix] = sc;
        float sb = 0.f;
        for (int c = 0; c < 64; c++) {
            const float f = (qs[c * 100 + pix] - mu) * sc;
            const float fb = __bfloat162float(__float2bfloat16(f));
            sb += fb * fb;
        }
        snDst[pix] = KSCALE * sb;
    }
    __syncthreads();

    for (int idx = tid; idx < 6400; idx += 256) {
        const int pt = idx >> 6, c = idx & 63;
        const float f = (qs[c * 100 + pt] - mean_s[pt]) * scal_s[pt];
        featDst[idx] = __float2bfloat16(f);
    }
    if (padrows) {
        for (int t = tid; t < padrows; t += 256) snDst[100 + t] = -721.f;
        for (int t = tid; t < padrows * 64; t += 256)
            featDst[100 * 64 + t] = __float2bfloat16(0.f);
    }
}

// ---------------------------------------------------------------------------
// Gram: 128x64 subtiles, 32x32 warp tiles, occ 3.
//   [0,750)   QS: T=8  | [750,780) SS upper-tri {8,8,4} | [780,930) QQ: T=2
// Hoisted XOR-swizzle addressing; f16x2 arg + ex2 epilogue.
// ---------------------------------------------------------------------------
__constant__ int c_ssI[10] = {0, 0, 0, 0, 1, 1, 1, 2, 2, 3};
__constant__ int c_ssJ[10] = {0, 1, 2, 3, 1, 2, 3, 2, 3, 3};
__constant__ float c_ssW[10] = {1.f, 2.f, 2.f, 2.f, 1.f, 2.f, 2.f, 1.f, 2.f, 1.f};

__global__ __launch_bounds__(256, 3)
void gram_tc(const int* __restrict__ qy, float* __restrict__ out) {
    extern __shared__ char smc[];
    float* snAs = (float*)(smc + 49152);
    float* snBs = (float*)(smc + 51200);
    float* red = (float*)(smc + 53248);
    float* red2 = (float*)(smc + 53280);
    int* sflag = (int*)(smc + 53888);
    const uint32_t smem_base = smem_to_u32(smc);

    const int tid = threadIdx.x;
    const int wid = tid >> 5, l = tid & 31;
    const int bid = blockIdx.x;

    // ---- decode ----
    const char *Abase, *Bbase;
    const float *snAg, *snBg;
    float* outp;
    int T, mode, ssStart = 0;
    if (bid < 750) {
        const int p = bid;
        const int w = p % 5, bq = p / 5, b = bq / 75;
        Abase = (const char*)(g_supB + (size_t)(b * 5 + w) * 512 * 64);
        Bbase = (const char*)(g_qryB + (size_t)bq * 128 * 64);
        snAg = g_snS + (b * 5 + w) * 512;
        snBg = g_snQ + bq * 128;
        outp = &g_accQS[p];
        T = 8; mode = 0;
    } else if (bid < 780) {
        const int g = bid - 750;
        const int p = g / 3, grp = g - p * 3;
        Abase = (const char*)(g_supB + (size_t)p * 512 * 64);
        Bbase = Abase;
        snAg = g_snS + p * 512;
        snBg = snAg;
        outp = &g_accSS[p];
        T = (grp == 2) ? 4 : 8; mode = 1; ssStart = grp * 4;
    } else {
        const int p = bid - 780;
        Abase = (const char*)(g_qryB + (size_t)p * 128 * 64);
        Bbase = Abase;
        snAg = g_snQ + p * 128;
        snBg = snAg;
        outp = &g_accQQ[p];
        T = 2; mode = 2;
    }

    auto geom = [&](int t, int& i0, int& j0, float& w) {
        if (mode == 1) {
            const int pair = ssStart + (t >> 1);
            i0 = c_ssI[pair] * 128;
            j0 = c_ssJ[pair] * 128 + (t & 1) * 64;
            w = c_ssW[pair];
        } else {
            i0 = (mode == 0) ? (t >> 1) * 128 : 0;
            j0 = (t & 1) * 64;
            w = 1.f;
        }
    };

    // per-thread cp.async geometry
    int loffA[4], lswA[4], loffB[2], lswB[2];
#pragma unroll
    for (int it = 0; it < 4; it++) {
        const int idx = it * 256 + tid;
        loffA[it] = (idx >> 3) * 128 + (idx & 7) * 16;
        lswA[it] = SMEM_SWIZZLE_128B(loffA[it]);
    }
#pragma unroll
    for (int it = 0; it < 2; it++) {
        const int idx = it * 256 + tid;
        loffB[it] = (idx >> 3) * 128 + (idx & 7) * 16;
        lswB[it] = SMEM_SWIZZLE_128B(loffB[it]);
    }

    // prologue: tiles 0 and 1 (T >= 2 in all modes)
#pragma unroll
    for (int t = 0; t < 2; t++) {
        int i0, j0; float w;
        geom(t, i0, j0, w);
        const char* Ar = Abase + (size_t)i0 * 128;
        const char* Br = Bbase + (size_t)j0 * 128;
        const uint32_t aOff = smem_base + t * 16384;
        const uint32_t bOff = smem_base + 32768 + t * 8192;
#pragma unroll
        for (int it = 0; it < 4; it++) cp16(aOff + lswA[it], Ar + loffA[it]);
#pragma unroll
        for (int it = 0; it < 2; it++) cp16(bOff + lswB[it], Br + loffB[it]);
        CP_COMMIT();
    }

    // sn staging
#pragma unroll
    for (int i = 0; i < 2; i++) {
        snAs[tid + i * 256] = snAg[tid + i * 256];
        snBs[tid + i * 256] = snBg[tid + i * 256];
    }

    const int wm = wid & 3, wn = wid >> 2;   // 4 x 2: 32 rows x 32 cols
    const int arow_l = l & 15;
    const int acol_l = ((l >> 4) & 1) * 16;
    const int brow_l = l & 7;
    const int bcol_l = ((l >> 3) & 1) * 16;
    const int qrow = l >> 2, qcol = (l & 3) * 2;
    const __half2 one2h = __float2half2_rn(1.f);
    const __half2 k2h = __float2half2_rn(TWO_KSCALE);

    // hoisted swizzled ldsm offsets (buffer 0, ki 0); per access XOR-in
    // the buffer bit and ki*32 (valid: disjoint bit ranges, masks unchanged)
    uint32_t aS[2], bS[4];
#pragma unroll
    for (int mi = 0; mi < 2; mi++) {
        const int off = (wm * 32 + mi * 16 + arow_l) * 128 + acol_l;
        aS[mi] = SMEM_SWIZZLE_128B(off);
    }
#pragma unroll
    for (int ni = 0; ni < 4; ni++) {
        const int off = (wn * 32 + ni * 8 + brow_l) * 128 + bcol_l;
        bS[ni] = SMEM_SWIZZLE_128B(off);
    }

    float blockSum = 0.f;

    for (int t = 0; t < T; t++) {
        int i0, j0; float tw;
        geom(t, i0, j0, tw);
        const int nl = (mode != 1 && (j0 & 64) && wn == 1) ? 1 : 4;

        if (t + 1 < T)
            asm volatile("cp.async.wait_group 1;" ::: "memory");
        else
            asm volatile("cp.async.wait_group 0;" ::: "memory");
        __syncthreads();

        const uint32_t aBufBase = smem_base + ((t & 1) << 14);
        const uint32_t bBufBase = smem_base + 32768 + ((t & 1) << 13);

        float acc[2][4][4];
#pragma unroll
        for (int mi = 0; mi < 2; mi++)
#pragma unroll
            for (int ni = 0; ni < 4; ni++)
#pragma unroll
                for (int e = 0; e < 4; e++) acc[mi][ni][e] = 0.f;

#pragma unroll
        for (int ki = 0; ki < 4; ki++) {
            const uint32_t kx = (uint32_t)(ki << 5);
            uint32_t af[2][4], bf[4][2];
#pragma unroll
            for (int mi = 0; mi < 2; mi++)
                ldsm_x4(af[mi][0], af[mi][1], af[mi][2], af[mi][3],
                        aBufBase + (aS[mi] ^ kx));
#pragma unroll
            for (int ni = 0; ni < 4; ni++)
                if (ni < nl)
                    ldsm_x2(bf[ni][0], bf[ni][1], bBufBase + (bS[ni] ^ kx));
#pragma unroll
            for (int mi = 0; mi < 2; mi++)
#pragma unroll
                for (int ni = 0; ni < 4; ni++)
                    if (ni < nl) mma16816(acc[mi][ni], af[mi], bf[ni]);
        }

        // ---- f16x2 epilogue: arg2 = k2h*dot2 + (sb2h + sa2h); t = ex2 ----
        __half2 sbh[4];
#pragma unroll
        for (int ni = 0; ni < 4; ni++)
            sbh[ni] = __floats2half2_rn(snBs[j0 + wn * 32 + ni * 8 + qcol],
                                        snBs[j0 + wn * 32 + ni * 8 + qcol + 1]);
        __half2 sah[4];
#pragma unroll
        for (int mi = 0; mi < 2; mi++) {
            sah[mi * 2 + 0] =
                __float2half2_rn(snAs[i0 + wm * 32 + mi * 16 + qrow]);
            sah[mi * 2 + 1] =
                __float2half2_rn(snAs[i0 + wm * 32 + mi * 16 + qrow + 8]);
        }

        float tileSum = 0.f;
#pragma unroll
        for (int mi = 0; mi < 2; mi++) {
            __half2 accH = __float2half2_rn(0.f);
#pragma unroll
            for (int ni = 0; ni < 4; ni++) {
                if (ni < nl) {
#pragma unroll
                    for (int hh = 0; hh < 2; hh++) {
                        const __half2 dot2 = __floats2half2_rn(
                            acc[mi][ni][hh * 2 + 0], acc[mi][ni][hh * 2 + 1]);
                        const __half2 sab =
                            __hadd2(sbh[ni], sah[mi * 2 + hh]);
                        const __half2 tt = h2ex2(__hfma2(k2h, dot2, sab));
                        const __half2 t2 = __hmul2(tt, tt);
                        const __half2 t4 = __hmul2(t2, t2);
                        const __half2 t8 = __hmul2(t4, t4);
                        __half2 w = __hfma2(t4, __hadd2(t8, one2h), one2h);
                        w = __hfma2(t2, w, one2h);
                        accH = __hadd2(accH, __hfma2(t2, w, tt));
                    }
                }
            }
            const float2 f2 = __half22float2(accH);
            tileSum += f2.x + f2.y;
        }
        blockSum = fmaf(tw, tileSum, blockSum);

        __syncthreads();  // buf[t&1] reads done before overwrite
        if (t + 2 < T) {
            int i2, j2; float w2;
            geom(t + 2, i2, j2, w2);
            const char* Ar = Abase + (size_t)i2 * 128;
            const char* Br = Bbase + (size_t)j2 * 128;
            const uint32_t aOff = smem_base + (t & 1) * 16384;
            const uint32_t bOff = smem_base + 32768 + (t & 1) * 8192;
#pragma unroll
            for (int it = 0; it < 4; it++)
                cp16(aOff + lswA[it], Ar + loffA[it]);
#pragma unroll
            for (int it = 0; it < 2; it++)
                cp16(bOff + lswB[it], Br + loffB[it]);
            CP_COMMIT();
        }
    }

    // ---- block reduce + atomic ----
#pragma unroll
    for (int o = 16; o; o >>= 1)
        blockSum += __shfl_xor_sync(0xffffffffu, blockSum, o);
    if (l == 0) red[wid] = blockSum;
    __syncthreads();
    if (tid == 0) {
        float tot = 0.f;
#pragma unroll
        for (int w = 0; w < 8; w++) tot += red[w];
        atomicAdd(outp, tot);
        __threadfence();
        const unsigned int old = atomicAdd(&g_done, 1u);
        *sflag = (old == NBLK_GRAM - 1) ? 1 : 0;
    }
    __syncthreads();

    // ---- last finishing block: final loss ----
    if (*sflag) {
        const int r = tid;
        float val = 0.f;
        if (r < 150) {
            const int b = r / 75;
            const float mq = (__ldcg(&g_accQQ[r]) - 500.f) * (1.f / 9900.f);
            float lg[5];
#pragma unroll
            for (int w = 0; w < 5; w++) {
                const float ms =
                    (__ldcg(&g_accSS[b * 5 + w]) - 2500.f) * (1.f / 249500.f);
                const float msq = (-2.f / 50000.f) * __ldcg(&g_accQS[r * 5 + w]);
                lg[w] = -(ms + mq + msq) * (1.f / 12.5f);
            }
            float m = lg[0];
#pragma unroll
            for (int w = 1; w < 5; w++) m = fmaxf(m, lg[w]);
            float Z = 0.f;
#pragma unroll
            for (int w = 0; w < 5; w++) Z += expf(lg[w] - m);
            const float lse = m + logf(Z);
            val = lse - lg[qy[r]];
        }
        if (r < 152) red2[r] = (r < 150) ? val : 0.f;
        __syncthreads();
        if (r == 0) {
            float s = 0.f;
            for (int i = 0; i < 150; i++) s += red2[i];
            out[0] = s * (1.f / 150.f);
        }
    }
}

// ---------------------------------------------------------------------------
extern "C" void kernel_launch(void* const* d_in, const int* in_sizes, int n_in,
                              void* d_out, int out_size) {
    const float* sup = (const float*)d_in[0];
    const float* qry = (const float*)d_in[1];
    const int* qy = (const int*)d_in[3];
    const float* Wk = (const float*)d_in[4];
    const float* Wq = (const float*)d_in[5];
    const float* Wv = (const float*)d_in[6];

    cudaFuncSetAttribute(preproc_kernel,
                         cudaFuncAttributeMaxDynamicSharedMemorySize,
                         (int)PRE_SMEM_BYTES);
    cudaFuncSetAttribute(gram_tc,
                         cudaFuncAttributeMaxDynamicSharedMemorySize,
                         (int)GRAM_SMEM_BYTES);

    preproc_kernel<<<NIMG, 256, PRE_SMEM_BYTES>>>(sup, qry, Wk, Wq, Wv);
    gram_tc<<<NBLK_GRAM, 256, GRAM_SMEM_BYTES>>>(qy, (float*)d_out);
}

// round 15
// speedup vs baseline: 1.3637x; 1.2400x over previous
#include <cuda_runtime.h>
#include <cuda_bf16.h>
#include <cuda_fp16.h>
#include <math.h>
#include <cstdint>

// ---------------------------------------------------------------------------
// B=2, N_WAY=5, K_SHOT=5, C=64, H=W=10 (n=100), Q=75, PROJ=64, NHEAD=8
// ALPHAS {8,4,2,1,0.5} -> sum_a exp(-a d) = t + t^2 + t^4 + t^8 + t^16,
// t = exp2(KSCALE * d).  sn arrays store KSCALE*|x|^2; pads = -721 so the
// epilogue needs no masking (t underflows to exactly 0).
// Preproc: proj GEMM (mma.sync k16) AND attention (mma.sync m16n8k8,
//          1 warp/head, P kept in registers via C->A fragment identity).
// Gram: identical to round-13 (validated 46.9us).
// ---------------------------------------------------------------------------

#define NSUP_IMG 50
#define NIMG 200
#define NBLK_GRAM 930

__device__ __align__(16) __nv_bfloat16 g_supB[10 * 512 * 64];
__device__ __align__(16) __nv_bfloat16 g_qryB[150 * 128 * 64];
__device__ __align__(16) float g_snS[10 * 512];
__device__ __align__(16) float g_snQ[150 * 128 + 512];
__device__ float g_accSS[10];
__device__ float g_accQQ[150];
__device__ float g_accQS[750];
__device__ unsigned int g_done;

// preproc smem layout (bytes):
//  aW 0..24576 | xB 24576..38912 | qB 38912..53248 | kB 53248..67584 |
//  vB 67584..82944 (stride 120 j) | qs f32 82944..108544 | stats 108544..
#define PRE_SMEM_BYTES 109568
#define XB_OFF 24576
#define QB_OFF 38912
#define KB_OFF 53248
#define VB_OFF 67584
#define QS_OFF 82944
#define ST_OFF 108544

#define GRAM_SMEM_BYTES 54016

#define SMEM_SWIZZLE_128B(off) ((off) ^ (((off) >> 3) & 0x70))
#define KSCALE (-0.72134752044448f)
#define TWO_KSCALE (1.44269504088896f)
#define QSC 0.51011856f /* log2(e)/sqrt(8) */

__device__ __forceinline__ uint32_t smem_to_u32(const void* p) {
    uint32_t a;
    asm("{ .reg .u64 t; cvta.to.shared.u64 t, %1; cvt.u32.u64 %0, t; }"
        : "=r"(a) : "l"(p));
    return a;
}
__device__ __forceinline__ float ex2f(float x) {
    float y;
    asm("ex2.approx.f32 %0, %1;" : "=f"(y) : "f"(x));
    return y;
}
__device__ __forceinline__ __half2 h2ex2(__half2 x) {
    uint32_t xi, yi;
    xi = *reinterpret_cast<uint32_t*>(&x);
    asm("ex2.approx.f16x2 %0, %1;" : "=r"(yi) : "r"(xi));
    return *reinterpret_cast<__half2*>(&yi);
}
__device__ __forceinline__ void ldsm_x4(uint32_t& r0, uint32_t& r1,
                                        uint32_t& r2, uint32_t& r3,
                                        uint32_t addr) {
    asm volatile("ldmatrix.sync.aligned.m8n8.x4.shared.b16 {%0,%1,%2,%3}, [%4];"
                 : "=r"(r0), "=r"(r1), "=r"(r2), "=r"(r3) : "r"(addr));
}
__device__ __forceinline__ void ldsm_x2(uint32_t& r0, uint32_t& r1,
                                        uint32_t addr) {
    asm volatile("ldmatrix.sync.aligned.m8n8.x2.shared.b16 {%0,%1}, [%2];"
                 : "=r"(r0), "=r"(r1) : "r"(addr));
}
__device__ __forceinline__ void mma16816(float* d, const uint32_t* a,
                                         const uint32_t* b) {
    asm volatile(
        "mma.sync.aligned.m16n8k16.row.col.f32.bf16.bf16.f32 "
        "{%0,%1,%2,%3}, {%4,%5,%6,%7}, {%8,%9}, {%0,%1,%2,%3};"
        : "+f"(d[0]), "+f"(d[1]), "+f"(d[2]), "+f"(d[3])
        : "r"(a[0]), "r"(a[1]), "r"(a[2]), "r"(a[3]), "r"(b[0]), "r"(b[1]));
}
__device__ __forceinline__ void mma16808(float* d, uint32_t a0, uint32_t a1,
                                         uint32_t b) {
    asm volatile(
        "mma.sync.aligned.m16n8k8.row.col.f32.bf16.bf16.f32 "
        "{%0,%1,%2,%3}, {%4,%5}, {%6}, {%0,%1,%2,%3};"
        : "+f"(d[0]), "+f"(d[1]), "+f"(d[2]), "+f"(d[3])
        : "r"(a0), "r"(a1), "r"(b));
}
__device__ __forceinline__ void cp16(uint32_t saddr, const char* g) {
    asm volatile("cp.async.cg.shared.global [%0], [%1], 16;"
                 :: "r"(saddr), "l"(__cvta_generic_to_global(g)) : "memory");
}
#define CP_COMMIT() asm volatile("cp.async.commit_group;" ::: "memory")

// ---------------------------------------------------------------------------
// Fused preproc, one block per image.
// ---------------------------------------------------------------------------
__global__ __launch_bounds__(256, 2)
void preproc_kernel(const float* __restrict__ sup_x,
                    const float* __restrict__ qry_x,
                    const float* __restrict__ Wk,
                    const float* __restrict__ Wq,
                    const float* __restrict__ Wv) {
    extern __shared__ char smc[];
    __nv_bfloat16* aW = (__nv_bfloat16*)smc;
    __nv_bfloat16* xB = (__nv_bfloat16*)(smc + XB_OFF);
    float* qsf = (float*)(smc + QS_OFF);
    float* mean_s = (float*)(smc + ST_OFF);
    float* scal_s = (float*)(smc + ST_OFF + 512);

    const int img = blockIdx.x;
    const int tid = threadIdx.x;
    const int wid = tid >> 5, l = tid & 31;

    if (img == 0) {
        if (tid < 10) g_accSS[tid] = 0.f;
        if (tid < 150) g_accQQ[tid] = 0.f;
        for (int t = tid; t < 750; t += 256) g_accQS[t] = 0.f;
        if (tid == 0) g_done = 0u;
    }

    const float* xg = (img < NSUP_IMG) ? (sup_x + (size_t)img * 6400)
                                       : (qry_x + (size_t)(img - NSUP_IMG) * 6400);

    // ---- phase 1a: W -> aW bf16 swizzled (192 rows x 128B) ----
#pragma unroll
    for (int it = 0; it < 12; it++) {
        const int f = tid + it * 256;
        const int row = f >> 4;
        const int q4 = f & 15;
        const float* Wsel = (row < 64) ? Wk : (row < 128) ? Wq : Wv;
        const float4 v = __ldg((const float4*)(Wsel + (row & 63) * 64 + q4 * 4));
        __nv_bfloat162 lo, hi;
        lo.x = __float2bfloat16(v.x); lo.y = __float2bfloat16(v.y);
        hi.x = __float2bfloat16(v.z); hi.y = __float2bfloat16(v.w);
        const int off = row * 128 + q4 * 8;
        const int sw = SMEM_SWIZZLE_128B(off);
        *(__nv_bfloat162*)((char*)aW + sw) = lo;
        *(__nv_bfloat162*)((char*)aW + sw + 4) = hi;
    }
    // ---- phase 1b: x^T -> xB bf16 swizzled; pad rows zero ----
    for (int t = tid; t < 384; t += 256)
        ((uint32_t*)((char*)xB + 100 * 128))[t] = 0u;
#pragma unroll
    for (int it = 0; it < 7; it++) {
        const int f = tid + it * 256;
        if (f < 1600) {
            const int c = f / 25;
            const int n4 = f - c * 25;
            const float4 v = *(const float4*)(xg + c * 100 + n4 * 4);
            const float vv[4] = {v.x, v.y, v.z, v.w};
#pragma unroll
            for (int j = 0; j < 4; j++) {
                const int off = (4 * n4 + j) * 128 + c * 2;
                *(__nv_bfloat16*)((char*)xB + SMEM_SWIZZLE_128B(off)) =
                    __float2bfloat16(vv[j]);
            }
        }
    }
    // ---- zero qB/kB pad rows (i/j 100..111) and vB pad cols (j 100..119) ----
    for (int t = tid; t < 384; t += 256) {
        const int h = t / 48, rem = t - h * 48;
        const int j = 100 + (rem >> 2), w = rem & 3;
        *(uint32_t*)(smc + QB_OFF + (h * 896 + j * 8) * 2 + w * 4) = 0u;
        *(uint32_t*)(smc + KB_OFF + (h * 896 + j * 8) * 2 + w * 4) = 0u;
    }
    for (int t = tid; t < 640; t += 256) {
        const int row = t / 10, jj = t - row * 10;
        *(uint32_t*)(smc + VB_OFF + (row * 120 + 100 + jj * 2) * 2) = 0u;
    }
    __syncthreads();

    // ---- phase 2: proj GEMM D[192][112] = W[192][64] * x^T[112][64]^T ----
    {
        const int wm = wid & 3, wn = wid >> 2;
        const uint32_t aB = smem_to_u32(aW);
        const uint32_t bB = smem_to_u32(xB);
        float acc[3][7][4];
#pragma unroll
        for (int mi = 0; mi < 3; mi++)
#pragma unroll
            for (int ni = 0; ni < 7; ni++)
#pragma unroll
                for (int e = 0; e < 4; e++) acc[mi][ni][e] = 0.f;

        const int arow_l = l & 15, acol_l = ((l >> 4) & 1) * 16;
        const int brow_l = l & 7, bcol_l = ((l >> 3) & 1) * 16;
#pragma unroll
        for (int ki = 0; ki < 4; ki++) {
            uint32_t af[3][4], bf[7][2];
#pragma unroll
            for (int mi = 0; mi < 3; mi++) {
                const int off =
                    (wm * 48 + mi * 16 + arow_l) * 128 + ki * 32 + acol_l;
                ldsm_x4(af[mi][0], af[mi][1], af[mi][2], af[mi][3],
                        aB + SMEM_SWIZZLE_128B(off));
            }
#pragma unroll
            for (int ni = 0; ni < 7; ni++) {
                const int off =
                    (wn * 56 + ni * 8 + brow_l) * 128 + ki * 32 + bcol_l;
                ldsm_x2(bf[ni][0], bf[ni][1], bB + SMEM_SWIZZLE_128B(off));
            }
#pragma unroll
            for (int mi = 0; mi < 3; mi++)
#pragma unroll
                for (int ni = 0; ni < 7; ni++)
                    mma16816(acc[mi][ni], af[mi], bf[ni]);
        }

        // store fragments as bf16 into qB [h][i][d], kB [h][j][d], vB [h][d][j]
#pragma unroll
        for (int mi = 0; mi < 3; mi++) {
            const int rowbase = wm * 48 + mi * 16;
            const int cat = rowbase >> 6;
#pragma unroll
            for (int ni = 0; ni < 7; ni++) {
                const int col0 = wn * 56 + ni * 8 + 2 * (l & 3);
                if (col0 < 100) {
#pragma unroll
                    for (int half = 0; half < 2; half++) {
                        const int r = rowbase + (l >> 2) + half * 8;
                        const float v0 = acc[mi][ni][half * 2];
                        const float v1 = acc[mi][ni][half * 2 + 1];
                        if (cat == 0) {
                            const int h = r >> 3, d = r & 7;
                            __nv_bfloat16* kb =
                                (__nv_bfloat16*)(smc + KB_OFF) + h * 896 +
                                col0 * 8 + d;
                            kb[0] = __float2bfloat16(v0);
                            kb[8] = __float2bfloat16(v1);
                        } else if (cat == 1) {
                            const int rr = r - 64, h = rr >> 3, d = rr & 7;
                            __nv_bfloat16* qb =
                                (__nv_bfloat16*)(smc + QB_OFF) + h * 896 +
                                col0 * 8 + d;
                            qb[0] = __float2bfloat16(v0 * QSC);
                            qb[8] = __float2bfloat16(v1 * QSC);
                        } else {
                            const int rr = r - 128, h = rr >> 3, d = rr & 7;
                            uint32_t pv;
                            asm("cvt.rn.bf16x2.f32 %0, %1, %2;"
                                : "=r"(pv) : "f"(v1), "f"(v0));
                            *(uint32_t*)(smc + VB_OFF +
                                         ((h * 8 + d) * 120 + col0) * 2) = pv;
                        }
                    }
                }
            }
        }
    }
    __syncthreads();

    // ---- phase 3: tensor-core attention, 1 warp per head ----
    {
        const int h = wid;
        const char* qBp = smc + QB_OFF + h * 1792;
        const char* kBp = smc + KB_OFF + h * 1792;
        const char* vBp = smc + VB_OFF + h * 1920;
        const char* xBp = smc + XB_OFF;
        const int c = l & 3, lq = l >> 2;

        for (int ch = 0; ch < 7; ch++) {
            const uint32_t qa0 =
                *(const uint32_t*)(qBp + (16 * ch + lq) * 16 + 4 * c);
            const uint32_t qa1 =
                *(const uint32_t*)(qBp + (16 * ch + lq + 8) * 16 + 4 * c);
            float sacc[13][4];
#pragma unroll
            for (int nt = 0; nt < 13; nt++)
#pragma unroll
                for (int e = 0; e < 4; e++) sacc[nt][e] = 0.f;
#pragma unroll
            for (int nt = 0; nt < 13; nt++) {
                const uint32_t kb =
                    *(const uint32_t*)(kBp + (8 * nt + lq) * 16 + 4 * c);
                mma16808(sacc[nt], qa0, qa1, kb);
            }
            if (c >= 2) {  // n-tile 12: j = 96+2c+e >= 100 invalid for c>=2
                sacc[12][0] = -1e30f; sacc[12][1] = -1e30f;
                sacc[12][2] = -1e30f; sacc[12][3] = -1e30f;
            }
            float z0 = 0.f, z1 = 0.f;
            uint32_t pa[13][2];
#pragma unroll
            for (int nt = 0; nt < 13; nt++) {
                const float e0 = ex2f(sacc[nt][0]), e1 = ex2f(sacc[nt][1]);
                const float e2 = ex2f(sacc[nt][2]), e3 = ex2f(sacc[nt][3]);
                z0 += e0 + e1;
                z1 += e2 + e3;
                asm("cvt.rn.bf16x2.f32 %0, %1, %2;"
                    : "=r"(pa[nt][0]) : "f"(e1), "f"(e0));
                asm("cvt.rn.bf16x2.f32 %0, %1, %2;"
                    : "=r"(pa[nt][1]) : "f"(e3), "f"(e2));
            }
            z0 += __shfl_xor_sync(0xffffffffu, z0, 1);
            z0 += __shfl_xor_sync(0xffffffffu, z0, 2);
            z1 += __shfl_xor_sync(0xffffffffu, z1, 1);
            z1 += __shfl_xor_sync(0xffffffffu, z1, 2);

            float oacc[4] = {0.f, 0.f, 0.f, 0.f};
#pragma unroll
            for (int kt = 0; kt < 13; kt++) {
                const uint32_t vb =
                    *(const uint32_t*)(vBp + lq * 240 + (8 * kt + 2 * c) * 2);
                mma16808(oacc, pa[kt][0], pa[kt][1], vb);
            }
            const float rz0 = 1.f / z0, rz1 = 1.f / z1;
            const int d0 = 2 * c;
            const int i0 = 16 * ch + lq;
            if (i0 < 100) {
                const __nv_bfloat162 xb = *(const __nv_bfloat162*)(
                    xBp + SMEM_SWIZZLE_128B(i0 * 128 + (h * 8 + d0) * 2));
                qsf[(h * 8 + d0) * 100 + i0] =
                    oacc[0] * rz0 + __bfloat162float(xb.x);
                qsf[(h * 8 + d0 + 1) * 100 + i0] =
                    oacc[1] * rz0 + __bfloat162float(xb.y);
            }
            const int i1 = i0 + 8;
            if (i1 < 100) {
                const __nv_bfloat162 xb = *(const __nv_bfloat162*)(
                    xBp + SMEM_SWIZZLE_128B(i1 * 128 + (h * 8 + d0) * 2));
                qsf[(h * 8 + d0) * 100 + i1] =
                    oacc[2] * rz1 + __bfloat162float(xb.x);
                qsf[(h * 8 + d0 + 1) * 100 + i1] =
                    oacc[3] * rz1 + __bfloat162float(xb.y);
            }
        }
    }
    __syncthreads();

    // ---- phase 4: destination + stats + emit ----
    __nv_bfloat16* featDst;
    float* snDst;
    int padrows;
    if (img < NSUP_IMG) {
        const int b = img / 25, s = img % 25;
        const int way = s / 5, shot = s % 5;
        featDst = g_supB + ((size_t)(b * 5 + way) * 512 + shot * 100) * 64;
        snDst = g_snS + (b * 5 + way) * 512 + shot * 100;
        padrows = (shot == 4) ? 12 : 0;
    } else {
        const int iq = img - NSUP_IMG;
        featDst = g_qryB + (size_t)iq * 128 * 64;
        snDst = g_snQ + iq * 128;
        padrows = 28;
    }

    if (tid < 100) {
        const int pix = tid;
        float s = 0.f, s2 = 0.f;
        for (int c = 0; c < 64; c++) {
            const float v = qsf[c * 100 + pix];
            s += v;
            s2 += v * v;
        }
        const float mu = s * (1.f / 64.f);
        float ss = fmaxf(s2 - s * mu, 0.f);
        const float sc = rsqrtf(ss + 1e-12f);
        mean_s[pix] = mu;
        scal_s[pix] = sc;
        float sb = 0.f;
        for (int c = 0; c < 64; c++) {
            const float f = (qsf[c * 100 + pix] - mu) * sc;
            const float fb = __bfloat162float(__float2bfloat16(f));
            sb += fb * fb;
        }
        snDst[pix] = KSCALE * sb;
    }
    __syncthreads();

    for (int idx = tid; idx < 6400; idx += 256) {
        const int pt = idx >> 6, c = idx & 63;
        const float f = (qsf[c * 100 + pt] - mean_s[pt]) * scal_s[pt];
        featDst[idx] = __float2bfloat16(f);
    }
    if (padrows) {
        for (int t = tid; t < padrows; t += 256) snDst[100 + t] = -721.f;
        for (int t = tid; t < padrows * 64; t += 256)
            featDst[100 * 64 + t] = __float2bfloat16(0.f);
    }
}

// ---------------------------------------------------------------------------
// Gram: identical to round 13 (validated).
// ---------------------------------------------------------------------------
__constant__ int c_ssI[10] = {0, 0, 0, 0, 1, 1, 1, 2, 2, 3};
__constant__ int c_ssJ[10] = {0, 1, 2, 3, 1, 2, 3, 2, 3, 3};
__constant__ float c_ssW[10] = {1.f, 2.f, 2.f, 2.f, 1.f, 2.f, 2.f, 1.f, 2.f, 1.f};

__global__ __launch_bounds__(256, 3)
void gram_tc(const int* __restrict__ qy, float* __restrict__ out) {
    extern __shared__ char smc[];
    float* snAs = (float*)(smc + 49152);
    float* snBs = (float*)(smc + 51200);
    float* red = (float*)(smc + 53248);
    float* red2 = (float*)(smc + 53280);
    int* sflag = (int*)(smc + 53888);
    const uint32_t smem_base = smem_to_u32(smc);

    const int tid = threadIdx.x;
    const int wid = tid >> 5, l = tid & 31;
    const int bid = blockIdx.x;

    const char *Abase, *Bbase;
    const float *snAg, *snBg;
    float* outp;
    int T, mode, ssStart = 0;
    if (bid < 750) {
        const int p = bid;
        const int w = p % 5, bq = p / 5, b = bq / 75;
        Abase = (const char*)(g_supB + (size_t)(b * 5 + w) * 512 * 64);
        Bbase = (const char*)(g_qryB + (size_t)bq * 128 * 64);
        snAg = g_snS + (b * 5 + w) * 512;
        snBg = g_snQ + bq * 128;
        outp = &g_accQS[p];
        T = 8; mode = 0;
    } else if (bid < 780) {
        const int g = bid - 750;
        const int p = g / 3, grp = g - p * 3;
        Abase = (const char*)(g_supB + (size_t)p * 512 * 64);
        Bbase = Abase;
        snAg = g_snS + p * 512;
        snBg = snAg;
        outp = &g_accSS[p];
        T = (grp == 2) ? 4 : 8; mode = 1; ssStart = grp * 4;
    } else {
        const int p = bid - 780;
        Abase = (const char*)(g_qryB + (size_t)p * 128 * 64);
        Bbase = Abase;
        snAg = g_snQ + p * 128;
        snBg = snAg;
        outp = &g_accQQ[p];
        T = 2; mode = 2;
    }

    auto geom = [&](int t, int& i0, int& j0, float& w) {
        if (mode == 1) {
            const int pair = ssStart + (t >> 1);
            i0 = c_ssI[pair] * 128;
            j0 = c_ssJ[pair] * 128 + (t & 1) * 64;
            w = c_ssW[pair];
        } else {
            i0 = (mode == 0) ? (t >> 1) * 128 : 0;
            j0 = (t & 1) * 64;
            w = 1.f;
        }
    };

    int loffA[4], lswA[4], loffB[2], lswB[2];
#pragma unroll
    for (int it = 0; it < 4; it++) {
        const int idx = it * 256 + tid;
        loffA[it] = (idx >> 3) * 128 + (idx & 7) * 16;
        lswA[it] = SMEM_SWIZZLE_128B(loffA[it]);
    }
#pragma unroll
    for (int it = 0; it < 2; it++) {
        const int idx = it * 256 + tid;
        loffB[it] = (idx >> 3) * 128 + (idx & 7) * 16;
        lswB[it] = SMEM_SWIZZLE_128B(loffB[it]);
    }

#pragma unroll
    for (int t = 0; t < 2; t++) {
        int i0, j0; float w;
        geom(t, i0, j0, w);
        const char* Ar = Abase + (size_t)i0 * 128;
        const char* Br = Bbase + (size_t)j0 * 128;
        const uint32_t aOff = smem_base + t * 16384;
        const uint32_t bOff = smem_base + 32768 + t * 8192;
#pragma unroll
        for (int it = 0; it < 4; it++) cp16(aOff + lswA[it], Ar + loffA[it]);
#pragma unroll
        for (int it = 0; it < 2; it++) cp16(bOff + lswB[it], Br + loffB[it]);
        CP_COMMIT();
    }

#pragma unroll
    for (int i = 0; i < 2; i++) {
        snAs[tid + i * 256] = snAg[tid + i * 256];
        snBs[tid + i * 256] = snBg[tid + i * 256];
    }

    const int wm = wid & 3, wn = wid >> 2;
    const int arow_l = l & 15;
    const int acol_l = ((l >> 4) & 1) * 16;
    const int brow_l = l & 7;
    const int bcol_l = ((l >> 3) & 1) * 16;
    const int qrow = l >> 2, qcol = (l & 3) * 2;
    const __half2 one2h = __float2half2_rn(1.f);
    const __half2 k2h = __float2half2_rn(TWO_KSCALE);

    uint32_t aS[2], bS[4];
#pragma unroll
    for (int mi = 0; mi < 2; mi++) {
        const int off = (wm * 32 + mi * 16 + arow_l) * 128 + acol_l;
        aS[mi] = SMEM_SWIZZLE_128B(off);
    }
#pragma unroll
    for (int ni = 0; ni < 4; ni++) {
        const int off = (wn * 32 + ni * 8 + brow_l) * 128 + bcol_l;
        bS[ni] = SMEM_SWIZZLE_128B(off);
    }

    float blockSum = 0.f;

    for (int t = 0; t < T; t++) {
        int i0, j0; float tw;
        geom(t, i0, j0, tw);
        const int nl = (mode != 1 && (j0 & 64) && wn == 1) ? 1 : 4;

        if (t + 1 < T)
            asm volatile("cp.async.wait_group 1;" ::: "memory");
        else
            asm volatile("cp.async.wait_group 0;" ::: "memory");
        __syncthreads();

        const uint32_t aBufBase = smem_base + ((t & 1) << 14);
        const uint32_t bBufBase = smem_base + 32768 + ((t & 1) << 13);

        float acc[2][4][4];
#pragma unroll
        for (int mi = 0; mi < 2; mi++)
#pragma unroll
            for (int ni = 0; ni < 4; ni++)
#pragma unroll
                for (int e = 0; e < 4; e++) acc[mi][ni][e] = 0.f;

#pragma unroll
        for (int ki = 0; ki < 4; ki++) {
            const uint32_t kx = (uint32_t)(ki << 5);
            uint32_t af[2][4], bf[4][2];
#pragma unroll
            for (int mi = 0; mi < 2; mi++)
                ldsm_x4(af[mi][0], af[mi][1], af[mi][2], af[mi][3],
                        aBufBase + (aS[mi] ^ kx));
#pragma unroll
            for (int ni = 0; ni < 4; ni++)
                if (ni < nl)
                    ldsm_x2(bf[ni][0], bf[ni][1], bBufBase + (bS[ni] ^ kx));
#pragma unroll
            for (int mi = 0; mi < 2; mi++)
#pragma unroll
                for (int ni = 0; ni < 4; ni++)
                    if (ni < nl) mma16816(acc[mi][ni], af[mi], bf[ni]);
        }

        __half2 sbh[4];
#pragma unroll
        for (int ni = 0; ni < 4; ni++)
            sbh[ni] = __floats2half2_rn(snBs[j0 + wn * 32 + ni * 8 + qcol],
                                        snBs[j0 + wn * 32 + ni * 8 + qcol + 1]);
        __half2 sah[4];
#pragma unroll
        for (int mi = 0; mi < 2; mi++) {
            sah[mi * 2 + 0] =
                __float2half2_rn(snAs[i0 + wm * 32 + mi * 16 + qrow]);
            sah[mi * 2 + 1] =
                __float2half2_rn(snAs[i0 + wm * 32 + mi * 16 + qrow + 8]);
        }

        float tileSum = 0.f;
#pragma unroll
        for (int mi = 0; mi < 2; mi++) {
            __half2 accH = __float2half2_rn(0.f);
#pragma unroll
            for (int ni = 0; ni < 4; ni++) {
                if (ni < nl) {
#pragma unroll
                    for (int hh = 0; hh < 2; hh++) {
                        const __half2 dot2 = __floats2half2_rn(
                            acc[mi][ni][hh * 2 + 0], acc[mi][ni][hh * 2 + 1]);
                        const __half2 sab =
                            __hadd2(sbh[ni], sah[mi * 2 + hh]);
                        const __half2 tt = h2ex2(__hfma2(k2h, dot2, sab));
                        const __half2 t2 = __hmul2(tt, tt);
                        const __half2 t4 = __hmul2(t2, t2);
                        const __half2 t8 = __hmul2(t4, t4);
                        __half2 w = __hfma2(t4, __hadd2(t8, one2h), one2h);
                        w = __hfma2(t2, w, one2h);
                        accH = __hadd2(accH, __hfma2(t2, w, tt));
                    }
                }
            }
            const float2 f2 = __half22float2(accH);
            tileSum += f2.x + f2.y;
        }
        blockSum = fmaf(tw, tileSum, blockSum);

        __syncthreads();
        if (t + 2 < T) {
            int i2, j2; float w2;
            geom(t + 2, i2, j2, w2);
            const char* Ar = Abase + (size_t)i2 * 128;
            const char* Br = Bbase + (size_t)j2 * 128;
            const uint32_t aOff = smem_base + (t & 1) * 16384;
            const uint32_t bOff = smem_base + 32768 + (t & 1) * 8192;
#pragma unroll
            for (int it = 0; it < 4; it++)
                cp16(aOff + lswA[it], Ar + loffA[it]);
#pragma unroll
            for (int it = 0; it < 2; it++)
                cp16(bOff + lswB[it], Br + loffB[it]);
            CP_COMMIT();
        }
    }

#pragma unroll
    for (int o = 16; o; o >>= 1)
        blockSum += __shfl_xor_sync(0xffffffffu, blockSum, o);
    if (l == 0) red[wid] = blockSum;
    __syncthreads();
    if (tid == 0) {
        float tot = 0.f;
#pragma unroll
        for (int w = 0; w < 8; w++) tot += red[w];
        atomicAdd(outp, tot);
        __threadfence();
        const unsigned int old = atomicAdd(&g_done, 1u);
        *sflag = (old == NBLK_GRAM - 1) ? 1 : 0;
    }
    __syncthreads();

    if (*sflag) {
        const int r = tid;
        float val = 0.f;
        if (r < 150) {
            const int b = r / 75;
            const float mq = (__ldcg(&g_accQQ[r]) - 500.f) * (1.f / 9900.f);
            float lg[5];
#pragma unroll
            for (int w = 0; w < 5; w++) {
                const float ms =
                    (__ldcg(&g_accSS[b * 5 + w]) - 2500.f) * (1.f / 249500.f);
                const float msq = (-2.f / 50000.f) * __ldcg(&g_accQS[r * 5 + w]);
                lg[w] = -(ms + mq + msq) * (1.f / 12.5f);
            }
            float m = lg[0];
#pragma unroll
            for (int w = 1; w < 5; w++) m = fmaxf(m, lg[w]);
            float Z = 0.f;
#pragma unroll
            for (int w = 0; w < 5; w++) Z += expf(lg[w] - m);
            const float lse = m + logf(Z);
            val = lse - lg[qy[r]];
        }
        if (r < 152) red2[r] = (r < 150) ? val : 0.f;
        __syncthreads();
        if (r == 0) {
            float s = 0.f;
            for (int i = 0; i < 150; i++) s += red2[i];
            out[0] = s * (1.f / 150.f);
        }
    }
}

// ---------------------------------------------------------------------------
extern "C" void kernel_launch(void* const* d_in, const int* in_sizes, int n_in,
                              void* d_out, int out_size) {
    const float* sup = (const float*)d_in[0];
    const float* qry = (const float*)d_in[1];
    const int* qy = (const int*)d_in[3];
    const float* Wk = (const float*)d_in[4];
    const float* Wq = (const float*)d_in[5];
    const float* Wv = (const float*)d_in[6];

    cudaFuncSetAttribute(preproc_kernel,
                         cudaFuncAttributeMaxDynamicSharedMemorySize,
                         (int)PRE_SMEM_BYTES);
    cudaFuncSetAttribute(gram_tc,
                         cudaFuncAttributeMaxDynamicSharedMemorySize,
                         (int)GRAM_SMEM_BYTES);

    preproc_kernel<<<NIMG, 256, PRE_SMEM_BYTES>>>(sup, qry, Wk, Wq, Wv);
    gram_tc<<<NBLK_GRAM, 256, GRAM_SMEM_BYTES>>>(qy, (float*)d_out);
}